// round 3
// baseline (speedup 1.0000x reference)
#include <cuda_runtime.h>

#define NN   25600
#define EE   409600
#define BB   128
#define EFE  1024
#define DD   128
#define LL   8
#define KK   32
#define NPGc 200

// ---------------- device scratch (static allocation, per harness rules) ----
__device__ float g_h[NN * DD];
__device__ float g_fni[NN * DD];
__device__ float g_fnj[NN * DD];
__device__ float g_hs[NN * DD];
__device__ float g_e0[EE * DD];
__device__ float g_e1[EE * DD];
__device__ float g_score[EE];
__device__ float g_aw[EE];
__device__ int   g_deg[NN];
__device__ int   g_rowptr[NN + 1];
__device__ int   g_eid[EE];
__device__ float g_m[NN];
__device__ float g_s[NN];
__device__ float g_hsort[NN * DD];
__device__ float g_rowmax[NN];
__device__ int   g_topk[BB * KK];
__device__ float g_pooled[BB * KK * DD];
__device__ float g_ft[BB * DD];
__device__ float g_al[BB];
__device__ float g_ar[BB];
__device__ float g_sc2[EFE];
__device__ float g_ex2[EFE];
__device__ float g_m2[BB];
__device__ float g_s2[BB];
__device__ float g_gagg[BB * DD];
__device__ float g_g2[BB * DD];

// ---------------- small helpers -------------------------------------------
__device__ __forceinline__ void atomicMaxF(float* addr, float val) {
    int* ia = (int*)addr;
    int old = *ia;
    while (__int_as_float(old) < val) {
        int assumed = old;
        old = atomicCAS(ia, assumed, __float_as_int(val));
        if (old == assumed) break;
    }
}

// ---------------- CSR build (dst-sorted edge list) -------------------------
__global__ void k_zero_deg() {
    int i = blockIdx.x * blockDim.x + threadIdx.x;
    if (i < NN) g_deg[i] = 0;
}
__global__ void k_count(const int* __restrict__ dst) {
    int e = blockIdx.x * blockDim.x + threadIdx.x;
    if (e < EE) atomicAdd(&g_deg[dst[e]], 1);
}
__global__ void k_scan() {
    // N = 25600 = 1024 threads * 25
    __shared__ int ssum[1024];
    int t = threadIdx.x;
    int start = t * 25;
    int vals[25];
    int local = 0;
#pragma unroll
    for (int i = 0; i < 25; i++) { vals[i] = g_deg[start + i]; local += vals[i]; }
    ssum[t] = local;
    __syncthreads();
    for (int off = 1; off < 1024; off <<= 1) {
        int v = (t >= off) ? ssum[t - off] : 0;
        __syncthreads();
        ssum[t] += v;
        __syncthreads();
    }
    int prefix = (t == 0) ? 0 : ssum[t - 1];
#pragma unroll
    for (int i = 0; i < 25; i++) { g_rowptr[start + i] = prefix; prefix += vals[i]; }
    if (t == 1023) g_rowptr[NN] = prefix;
}
__global__ void k_cursor() {
    int i = blockIdx.x * blockDim.x + threadIdx.x;
    if (i < NN) g_deg[i] = g_rowptr[i];
}
__global__ void k_scatter(const int* __restrict__ dst) {
    int e = blockIdx.x * blockDim.x + threadIdx.x;
    if (e < EE) {
        int p = atomicAdd(&g_deg[dst[e]], 1);
        g_eid[p] = e;
    }
}

// ---------------- embeddings ----------------------------------------------
__global__ void k_embed_h(const int* __restrict__ th, const float* __restrict__ emb) {
    int idx = blockIdx.x * blockDim.x + threadIdx.x;   // NN*32 float4 slots
    if (idx >= NN * 32) return;
    int n = idx >> 5, q = (idx & 31) << 2;
    float4 v = *(const float4*)(emb + th[n] * DD + q);
    v.x = fmaxf(v.x, 0.f); v.y = fmaxf(v.y, 0.f);
    v.z = fmaxf(v.z, 0.f); v.w = fmaxf(v.w, 0.f);
    *(float4*)&g_h[n * DD + q] = v;
}
__global__ void k_embed_e(const int* __restrict__ te, const float* __restrict__ emb) {
    int idx = blockIdx.x * blockDim.x + threadIdx.x;   // EE*32 float4 slots
    if (idx >= EE * 32) return;
    int e = idx >> 5, q = (idx & 31) << 2;
    float4 v = *(const float4*)(emb + te[e] * DD + q);
    *(float4*)&g_e0[(size_t)e * DD + q] = v;
}

// ---------------- tiled SGEMM: C(Mx128) = A(Mx128) @ W(128x128) ------------
// EPI 0: plain store; EPI 1: edge epilogue (gather add + leaky + score);
// EPI 2: +bias, relu.
template <int EPI>
__global__ void __launch_bounds__(256, 2)
sgemm_k(const float* __restrict__ A, const float* __restrict__ W,
        float* __restrict__ C,
        const float* __restrict__ fni, const float* __restrict__ fnj,
        const int* __restrict__ src, const int* __restrict__ dst,
        const float* __restrict__ bias, const float* __restrict__ attn,
        float* __restrict__ score) {
    __shared__ float As[8][132];
    __shared__ float Bs[8][128];
    __shared__ float rowsum[128];
    const int tid = threadIdx.x;
    const int tx = tid & 15, ty = tid >> 4;
    const int rowbase = blockIdx.x * 128;
    const int aRow = tid >> 1;
    const int aCol4 = (tid & 1) << 2;
    const int bRow = tid >> 5;
    const int bCol4 = (tid & 31) << 2;
    const float* Ab = A + (size_t)rowbase * DD;

    float acc[8][8];
#pragma unroll
    for (int i = 0; i < 8; i++)
#pragma unroll
        for (int j = 0; j < 8; j++) acc[i][j] = 0.f;

    for (int kt = 0; kt < 128; kt += 8) {
        float4 av = *(const float4*)(Ab + aRow * DD + kt + aCol4);
        As[aCol4 + 0][aRow] = av.x;
        As[aCol4 + 1][aRow] = av.y;
        As[aCol4 + 2][aRow] = av.z;
        As[aCol4 + 3][aRow] = av.w;
        *(float4*)&Bs[bRow][bCol4] = *(const float4*)(W + (kt + bRow) * DD + bCol4);
        __syncthreads();
#pragma unroll
        for (int k = 0; k < 8; k++) {
            float rm[8], rn[8];
#pragma unroll
            for (int i = 0; i < 8; i++) rm[i] = As[k][ty * 8 + i];
#pragma unroll
            for (int j = 0; j < 8; j++) rn[j] = Bs[k][tx * 8 + j];
#pragma unroll
            for (int i = 0; i < 8; i++)
#pragma unroll
                for (int j = 0; j < 8; j++) acc[i][j] = fmaf(rm[i], rn[j], acc[i][j]);
        }
        __syncthreads();
    }

    if (EPI == 0) {
#pragma unroll
        for (int i = 0; i < 8; i++) {
            size_t r = (size_t)(rowbase + ty * 8 + i);
            float4 o0 = {acc[i][0], acc[i][1], acc[i][2], acc[i][3]};
            float4 o1 = {acc[i][4], acc[i][5], acc[i][6], acc[i][7]};
            float4* pc = (float4*)(C + r * DD + tx * 8);
            pc[0] = o0; pc[1] = o1;
        }
    } else if (EPI == 2) {
        float br[8];
#pragma unroll
        for (int j = 0; j < 8; j++) br[j] = bias[tx * 8 + j];
#pragma unroll
        for (int i = 0; i < 8; i++) {
            size_t r = (size_t)(rowbase + ty * 8 + i);
            float v[8];
#pragma unroll
            for (int j = 0; j < 8; j++) v[j] = fmaxf(acc[i][j] + br[j], 0.f);
            float4 o0 = {v[0], v[1], v[2], v[3]};
            float4 o1 = {v[4], v[5], v[6], v[7]};
            float4* pc = (float4*)(C + r * DD + tx * 8);
            pc[0] = o0; pc[1] = o1;
        }
    } else {  // EPI == 1 : edge GEMM epilogue
        float br[8], at[8];
#pragma unroll
        for (int j = 0; j < 8; j++) { br[j] = bias[tx * 8 + j]; at[j] = attn[tx * 8 + j]; }
        if (tid < 128) rowsum[tid] = 0.f;
        __syncthreads();
#pragma unroll
        for (int i = 0; i < 8; i++) {
            int r = rowbase + ty * 8 + i;
            int sI = src[r], dI = dst[r];
            const float4* pn = (const float4*)(fni + sI * DD + tx * 8);
            const float4* pm = (const float4*)(fnj + dI * DD + tx * 8);
            float4 n0 = pn[0], n1 = pn[1], m0 = pm[0], m1 = pm[1];
            float v[8];
            v[0] = acc[i][0] + n0.x + m0.x + br[0];
            v[1] = acc[i][1] + n0.y + m0.y + br[1];
            v[2] = acc[i][2] + n0.z + m0.z + br[2];
            v[3] = acc[i][3] + n0.w + m0.w + br[3];
            v[4] = acc[i][4] + n1.x + m1.x + br[4];
            v[5] = acc[i][5] + n1.y + m1.y + br[5];
            v[6] = acc[i][6] + n1.z + m1.z + br[6];
            v[7] = acc[i][7] + n1.w + m1.w + br[7];
            float p = 0.f;
#pragma unroll
            for (int j = 0; j < 8; j++) {
                v[j] = v[j] > 0.f ? v[j] : 0.01f * v[j];
                p = fmaf(v[j], at[j], p);
            }
            float4 o0 = {v[0], v[1], v[2], v[3]};
            float4 o1 = {v[4], v[5], v[6], v[7]};
            float4* pc = (float4*)(C + (size_t)r * DD + tx * 8);
            pc[0] = o0; pc[1] = o1;
            atomicAdd(&rowsum[ty * 8 + i], p);
        }
        __syncthreads();
        if (tid < 128) score[rowbase + tid] = rowsum[tid];
    }
}

// ---------------- edge softmax (CSR, warp per node) ------------------------
__global__ void k_softmax() {
    int n = blockIdx.x * 8 + (threadIdx.x >> 5);
    int lane = threadIdx.x & 31;
    int beg = g_rowptr[n], end = g_rowptr[n + 1];
    float mx = -3.0e38f;
    for (int j = beg + lane; j < end; j += 32) mx = fmaxf(mx, g_score[g_eid[j]]);
#pragma unroll
    for (int o = 16; o > 0; o >>= 1) mx = fmaxf(mx, __shfl_xor_sync(0xffffffffu, mx, o));
    float sm = 0.f;
    for (int j = beg + lane; j < end; j += 32) sm += __expf(g_score[g_eid[j]] - mx);
#pragma unroll
    for (int o = 16; o > 0; o >>= 1) sm += __shfl_xor_sync(0xffffffffu, sm, o);
    if (lane == 0) { g_m[n] = mx; g_s[n] = sm; }
}
__global__ void k_weight(const int* __restrict__ dst) {
    int e = blockIdx.x * blockDim.x + threadIdx.x;
    if (e < EE) {
        int d = dst[e];
        g_aw[e] = __expf(g_score[e] - g_m[d]) / g_s[d];
    }
}
// aggregation: h[n] = relu(sum_in-edges aw[e] * hs[src[e]])   (warp per node)
__global__ void k_agg(const int* __restrict__ src) {
    int n = blockIdx.x * 8 + (threadIdx.x >> 5);
    int lane = threadIdx.x & 31;
    int beg = g_rowptr[n], end = g_rowptr[n + 1];
    float4 acc = {0.f, 0.f, 0.f, 0.f};
    for (int j = beg; j < end; j++) {
        int e = g_eid[j];
        float w = g_aw[e];
        int sI = src[e];
        float4 v = *(const float4*)&g_hs[sI * DD + lane * 4];
        acc.x = fmaf(w, v.x, acc.x);
        acc.y = fmaf(w, v.y, acc.y);
        acc.z = fmaf(w, v.z, acc.z);
        acc.w = fmaf(w, v.w, acc.w);
    }
    acc.x = fmaxf(acc.x, 0.f); acc.y = fmaxf(acc.y, 0.f);
    acc.z = fmaxf(acc.z, 0.f); acc.w = fmaxf(acc.w, 0.f);
    *(float4*)&g_h[n * DD + lane * 4] = acc;
}

// ---------------- SortPooling ----------------------------------------------
__global__ void k_sort() {
    __shared__ float s[128];
    int n = blockIdx.x, t = threadIdx.x;
    s[t] = g_fni[n * DD + t];  // hfinal lives in g_fni
    __syncthreads();
    for (int k = 2; k <= 128; k <<= 1)
        for (int j = k >> 1; j > 0; j >>= 1) {
            int ixj = t ^ j;
            if (ixj > t) {
                float a = s[t], b = s[ixj];
                bool up = ((t & k) == 0);
                if ((a > b) == up) { s[t] = b; s[ixj] = a; }
            }
            __syncthreads();
        }
    g_hsort[n * DD + t] = s[t];
    if (t == 127) g_rowmax[n] = s[127];
}
__global__ void k_topk() {
    __shared__ float v[256];
    __shared__ int   id[256];
    int b = blockIdx.x, t = threadIdx.x;
    if (t < NPGc) { v[t] = g_rowmax[b * NPGc + t]; id[t] = t; }
    else          { v[t] = -3.0e38f;              id[t] = 1000 + t; }
    __syncthreads();
    // sort: descending value, ties -> ascending id (matches lax.top_k)
    for (int k = 2; k <= 256; k <<= 1)
        for (int j = k >> 1; j > 0; j >>= 1) {
            int ixj = t ^ j;
            if (ixj > t) {
                bool up = ((t & k) == 0);
                float va = v[t], vb = v[ixj];
                int ia = id[t], ib = id[ixj];
                bool aAfterB = (va < vb) || (va == vb && ia > ib);
                bool sw = up ? aAfterB : !aAfterB;
                if (sw) { v[t] = vb; v[ixj] = va; id[t] = ib; id[ixj] = ia; }
            }
            __syncthreads();
        }
    if (t < KK) g_topk[b * KK + t] = id[t];
}
__global__ void k_gather() {
    int idx = blockIdx.x * blockDim.x + threadIdx.x;
    if (idx >= BB * KK * DD) return;
    int b = idx >> 12;
    int rem = idx & 4095;
    int k = rem >> 7;
    int d = rem & 127;
    int node = g_topk[b * KK + k];
    g_pooled[idx] = g_hsort[(b * NPGc + node) * DD + d];
}

// ---------------- graph-level GAT + head -----------------------------------
__global__ void k_ft(const float* __restrict__ W3) {
    int b = blockIdx.x, c = threadIdx.x;
    const float* pr = g_pooled + b * (KK * DD);
    float acc = 0.f;
#pragma unroll 8
    for (int kk = 0; kk < KK * DD; kk++) acc = fmaf(pr[kk], W3[kk * DD + c], acc);
    g_ft[b * DD + c] = acc;
}
__global__ void k_alar(const float* __restrict__ al3, const float* __restrict__ ar3) {
    int b = threadIdx.x;
    float a1 = 0.f, a2 = 0.f;
    for (int k = 0; k < DD; k++) {
        float f = g_ft[b * DD + k];
        a1 = fmaf(f, al3[k], a1);
        a2 = fmaf(f, ar3[k], a2);
    }
    g_al[b] = a1;
    g_ar[b] = a2;
}
__global__ void k_fg_init() {
    int i = blockIdx.x * blockDim.x + threadIdx.x;
    if (i < BB * DD) g_gagg[i] = 0.f;
    if (i < BB) { g_m2[i] = -3.0e38f; g_s2[i] = 0.f; }
}
__global__ void k_fg_score(const int* __restrict__ fs, const int* __restrict__ fd) {
    int e = blockIdx.x * blockDim.x + threadIdx.x;
    if (e < EFE) {
        float sc = g_al[fs[e]] + g_ar[fd[e]];
        sc = sc > 0.f ? sc : 0.2f * sc;
        g_sc2[e] = sc;
        atomicMaxF(&g_m2[fd[e]], sc);
    }
}
__global__ void k_fg_exp(const int* __restrict__ fd) {
    int e = blockIdx.x * blockDim.x + threadIdx.x;
    if (e < EFE) {
        float ex = __expf(g_sc2[e] - g_m2[fd[e]]);
        g_ex2[e] = ex;
        atomicAdd(&g_s2[fd[e]], ex);
    }
}
__global__ void k_fg_agg(const int* __restrict__ fs, const int* __restrict__ fd) {
    int idx = blockIdx.x * blockDim.x + threadIdx.x;
    if (idx >= EFE * 32) return;
    int e = idx >> 5, lane = idx & 31;
    float w = g_ex2[e] / g_s2[fd[e]];
    float4 v = *(const float4*)&g_ft[fs[e] * DD + lane * 4];
    float* o = &g_gagg[fd[e] * DD + lane * 4];
    atomicAdd(o + 0, w * v.x);
    atomicAdd(o + 1, w * v.y);
    atomicAdd(o + 2, w * v.z);
    atomicAdd(o + 3, w * v.w);
}
__global__ void k_gl(const float* __restrict__ b3, const float* __restrict__ Wl,
                     const float* __restrict__ bl) {
    __shared__ float sg[128];
    int b = blockIdx.x, t = threadIdx.x;
    float v = g_gagg[b * DD + t] + b3[t];
    sg[t] = fmaxf(v, 0.f);
    __syncthreads();
    float acc = bl[t];
    for (int k = 0; k < DD; k++) acc = fmaf(sg[k], Wl[k * DD + t], acc);
    g_g2[b * DD + t] = fmaxf(acc, 0.f);
}
__global__ void k_out(const float* __restrict__ Wc, const float* __restrict__ bc,
                      float* __restrict__ out) {
    int i = threadIdx.x;
    if (i < BB * 2) {
        int b = i >> 1, c = i & 1;
        float acc = bc[c];
        for (int k = 0; k < DD; k++) acc = fmaf(g_g2[b * DD + k], Wc[k * 2 + c], acc);
        out[i] = acc;
    }
}

// ---------------- launch ----------------------------------------------------
extern "C" void kernel_launch(void* const* d_in, const int* in_sizes, int n_in,
                              void* d_out, int out_size) {
    const int*   tokens_h   = (const int*)d_in[0];
    const int*   tokens_e   = (const int*)d_in[1];
    const int*   src        = (const int*)d_in[2];
    const int*   dst        = (const int*)d_in[3];
    const int*   fg_src     = (const int*)d_in[4];
    const int*   fg_dst     = (const int*)d_in[5];
    const float* token_emb  = (const float*)d_in[6];
    const float* e_token_emb= (const float*)d_in[7];
    const float* W_ni       = (const float*)d_in[8];
    const float* W_nj       = (const float*)d_in[9];
    const float* W_fij      = (const float*)d_in[10];
    const float* W_node     = (const float*)d_in[11];
    const float* attn_e     = (const float*)d_in[12];
    const float* bias_e     = (const float*)d_in[13];
    const float* Wf         = (const float*)d_in[14];
    const float* bf         = (const float*)d_in[15];
    const float* W3         = (const float*)d_in[16];
    const float* al3        = (const float*)d_in[17];
    const float* ar3        = (const float*)d_in[18];
    const float* b3         = (const float*)d_in[19];
    const float* Wl         = (const float*)d_in[20];
    const float* bl         = (const float*)d_in[21];
    const float* Wc         = (const float*)d_in[22];
    const float* bc         = (const float*)d_in[23];

    float *p_h, *p_fni, *p_fnj, *p_hs, *p_e0, *p_e1, *p_score;
    cudaGetSymbolAddress((void**)&p_h, g_h);
    cudaGetSymbolAddress((void**)&p_fni, g_fni);
    cudaGetSymbolAddress((void**)&p_fnj, g_fnj);
    cudaGetSymbolAddress((void**)&p_hs, g_hs);
    cudaGetSymbolAddress((void**)&p_e0, g_e0);
    cudaGetSymbolAddress((void**)&p_e1, g_e1);
    cudaGetSymbolAddress((void**)&p_score, g_score);

    // CSR build (dst is a fixed input; order-only nondeterminism is within fp tol)
    k_zero_deg<<<NN / 256, 256>>>();
    k_count<<<EE / 256, 256>>>(dst);
    k_scan<<<1, 1024>>>();
    k_cursor<<<NN / 256, 256>>>();
    k_scatter<<<EE / 256, 256>>>(dst);

    // embeddings
    k_embed_h<<<NN * 32 / 256, 256>>>(tokens_h, token_emb);
    k_embed_e<<<EE * 32 / 256, 256>>>(tokens_e, e_token_emb);

    for (int l = 0; l < LL; l++) {
        const float* Wni   = W_ni   + l * DD * DD;
        const float* Wnj   = W_nj   + l * DD * DD;
        const float* Wnode = W_node + l * DD * DD;
        const float* Wfij  = W_fij  + l * DD * DD;
        const float* bias  = bias_e + l * DD;
        const float* attn  = attn_e + l * DD;
        float* ein  = (l & 1) ? p_e1 : p_e0;
        float* eout = (l & 1) ? p_e0 : p_e1;

        sgemm_k<0><<<NN / 128, 256>>>(p_h, Wni, p_fni, nullptr, nullptr, nullptr,
                                      nullptr, nullptr, nullptr, nullptr);
        sgemm_k<0><<<NN / 128, 256>>>(p_h, Wnj, p_fnj, nullptr, nullptr, nullptr,
                                      nullptr, nullptr, nullptr, nullptr);
        sgemm_k<0><<<NN / 128, 256>>>(p_h, Wnode, p_hs, nullptr, nullptr, nullptr,
                                      nullptr, nullptr, nullptr, nullptr);
        sgemm_k<1><<<EE / 128, 256>>>(ein, Wfij, eout, p_fni, p_fnj, src, dst,
                                      bias, attn, p_score);
        k_softmax<<<NN / 8, 256>>>();
        k_weight<<<EE / 256, 256>>>(dst);
        k_agg<<<NN / 8, 256>>>(src);
    }

    // hfinal = relu(h @ Wf + bf)  -> g_fni
    sgemm_k<2><<<NN / 128, 256>>>(p_h, Wf, p_fni, nullptr, nullptr, nullptr,
                                  nullptr, bf, nullptr, nullptr);

    k_sort<<<NN, 128>>>();
    k_topk<<<BB, 256>>>();
    k_gather<<<BB * KK * DD / 256, 256>>>();
    k_ft<<<BB, DD>>>(W3);
    k_alar<<<1, BB>>>(al3, ar3);
    k_fg_init<<<BB * DD / 256, 256>>>();
    k_fg_score<<<EFE / 256, 256>>>(fg_src, fg_dst);
    k_fg_exp<<<EFE / 256, 256>>>(fg_dst);
    k_fg_agg<<<EFE * 32 / 256, 256>>>(fg_src, fg_dst);
    k_gl<<<BB, DD>>>(b3, Wl, bl);
    k_out<<<1, 256>>>(Wc, bc, (float*)d_out);
}

// round 9
// speedup vs baseline: 1.6788x; 1.6788x over previous
#include <cuda_runtime.h>
#include <cuda_bf16.h>
#include <cstdint>

#define NN   25600
#define EE   409600
#define BB   128
#define EFE  1024
#define DD   128
#define LL   8
#define KK   32
#define NPGc 200

// ---------------- device scratch -------------------------------------------
__device__ float g_h[NN * DD];
__device__ float g_fni[NN * DD];
__device__ float g_fnj[NN * DD];
__device__ float g_hs[NN * DD];
__device__ float g_e0[EE * DD];
__device__ float g_e1[EE * DD];
__device__ float g_score[EE];
__device__ float g_aw[EE];
__device__ int   g_deg[NN];
__device__ int   g_rowptr[NN + 1];
__device__ int   g_eid[EE];
__device__ float g_m[NN];
__device__ float g_s[NN];
__device__ float g_hsort[NN * DD];
__device__ float g_rowmax[NN];
__device__ int   g_topk[BB * KK];
__device__ float g_pooled[BB * KK * DD];
__device__ float g_ft[BB * DD];
__device__ float g_al[BB];
__device__ float g_ar[BB];
__device__ float g_sc2[EFE];
__device__ float g_ex2[EFE];
__device__ float g_m2[BB];
__device__ float g_s2[BB];
__device__ float g_gagg[BB * DD];
__device__ float g_g2[BB * DD];
// transposed + bf16-split weights: WT[n][k]
__device__ __align__(16) __nv_bfloat16 g_wT_hi[DD * DD];
__device__ __align__(16) __nv_bfloat16 g_wT_lo[DD * DD];

// ---------------- PTX helpers (baseline ISA only: ldmatrix + mma.sync) -----
__device__ __forceinline__ uint32_t smem_u32(const void* p) {
    uint32_t a;
    asm("{ .reg .u64 t; cvta.to.shared.u64 t, %1; cvt.u32.u64 %0, t; }"
        : "=r"(a) : "l"(p));
    return a;
}
__device__ __forceinline__ void ldm4(uint32_t* r, uint32_t addr) {
    asm volatile("ldmatrix.sync.aligned.m8n8.x4.shared.b16 {%0,%1,%2,%3}, [%4];"
                 : "=r"(r[0]), "=r"(r[1]), "=r"(r[2]), "=r"(r[3]) : "r"(addr));
}
__device__ __forceinline__ void mma_bf16(float* c, const uint32_t* a,
                                         uint32_t b0, uint32_t b1) {
    asm volatile(
        "mma.sync.aligned.m16n8k16.row.col.f32.bf16.bf16.f32 "
        "{%0,%1,%2,%3}, {%4,%5,%6,%7}, {%8,%9}, {%0,%1,%2,%3};"
        : "+f"(c[0]), "+f"(c[1]), "+f"(c[2]), "+f"(c[3])
        : "r"(a[0]), "r"(a[1]), "r"(a[2]), "r"(a[3]), "r"(b0), "r"(b1));
}
__device__ __forceinline__ uint32_t packbf(__nv_bfloat16 a, __nv_bfloat16 b) {
    __nv_bfloat162 t;
    t.x = a; t.y = b;
    return *(uint32_t*)&t;
}

// ---------------- weight prep: WT_hi/lo[n][k] = split(W[k][n]) --------------
__global__ void k_prepW(const float* __restrict__ W) {
    int idx = blockIdx.x * blockDim.x + threadIdx.x;   // 16384
    int n = idx >> 7, k = idx & 127;
    float v = W[k * DD + n];
    __nv_bfloat16 hi = __float2bfloat16(v);
    float lo = v - __bfloat162float(hi);
    g_wT_hi[n * DD + k] = hi;
    g_wT_lo[n * DD + k] = __float2bfloat16(lo);
}

// ---------------- mma.sync GEMM: C(Mx128) = A(Mx128) @ W --------------------
// 3-term bf16 split (hi*hi + hi*lo + lo*hi) for ~1.5e-5 accuracy.
// CTA: 128x128 tile, 256 thr (8 warps, 4x2), warp tile 32x64.
// EPI 0: plain; EPI 1: edge epilogue (gather+bias+leaky+score); EPI 2: +bias relu
#define PADK   136                       // bf16 elements per smem row (272 B)
#define ROWB   (PADK * 2)
#define BUFSZ  (128 * ROWB)              // 34816 B
#define OFF_AH 0
#define OFF_AL BUFSZ
#define OFF_BH (2 * BUFSZ)
#define OFF_BL (3 * BUFSZ)
#define SMEM_SZ (4 * BUFSZ)              // 139264 B

template <int EPI>
__global__ void __launch_bounds__(256)
tc_gemm(const float* __restrict__ A, float* __restrict__ C,
        const float* __restrict__ fni, const float* __restrict__ fnj,
        const int* __restrict__ src, const int* __restrict__ dst,
        const float* __restrict__ bias, const float* __restrict__ attn,
        float* __restrict__ score) {
    extern __shared__ char smem[];
    const uint32_t sb = smem_u32(smem);
    const int tid = threadIdx.x;
    const int rowbase = blockIdx.x * 128;

    // ---- stage A: fp32 -> bf16 hi/lo, padded rows --------------------------
    const float* Ab = A + (size_t)rowbase * DD;
#pragma unroll
    for (int i = 0; i < 16; i++) {
        int idx = tid + (i << 8);           // 0..4095 float4 chunks
        int r = idx >> 5, k4 = (idx & 31) << 2;
        float4 v = *(const float4*)(Ab + r * DD + k4);
        __nv_bfloat16 h0 = __float2bfloat16(v.x), h1 = __float2bfloat16(v.y);
        __nv_bfloat16 h2 = __float2bfloat16(v.z), h3 = __float2bfloat16(v.w);
        __nv_bfloat16 l0 = __float2bfloat16(v.x - __bfloat162float(h0));
        __nv_bfloat16 l1 = __float2bfloat16(v.y - __bfloat162float(h1));
        __nv_bfloat16 l2 = __float2bfloat16(v.z - __bfloat162float(h2));
        __nv_bfloat16 l3 = __float2bfloat16(v.w - __bfloat162float(h3));
        uint2 hh; hh.x = packbf(h0, h1); hh.y = packbf(h2, h3);
        uint2 ll; ll.x = packbf(l0, l1); ll.y = packbf(l2, l3);
        int off = r * ROWB + k4 * 2;
        *(uint2*)(smem + OFF_AH + off) = hh;
        *(uint2*)(smem + OFF_AL + off) = ll;
    }
    // ---- stage B: pre-split WT (n-major, k contiguous) ---------------------
#pragma unroll
    for (int i = 0; i < 8; i++) {
        int idx = tid + (i << 8);           // 0..2047 uint4 chunks (8 bf16)
        int n = idx >> 4, k8 = (idx & 15) << 3;
        int off = n * ROWB + k8 * 2;
        *(uint4*)(smem + OFF_BH + off) = *(const uint4*)(g_wT_hi + n * DD + k8);
        *(uint4*)(smem + OFF_BL + off) = *(const uint4*)(g_wT_lo + n * DD + k8);
    }
    __syncthreads();

    const int wid = tid >> 5, lane = tid & 31;
    const int wm = wid & 3, wn = wid >> 2;      // warp grid 4 (M) x 2 (N)

    float c[2][8][4] = {};                       // [mblk16][ntile8][frag]

    // ldmatrix per-lane addresses
    const uint32_t aoff = (uint32_t)(wm * 32 + (lane & 15)) * ROWB + (lane >> 4) * 16;
    const uint32_t boff = (uint32_t)(wn * 64 + (lane & 7) + ((lane >> 4) & 1) * 8) * ROWB
                        + ((lane >> 3) & 1) * 16;
    const uint32_t sAh = sb + OFF_AH + aoff, sAl = sb + OFF_AL + aoff;
    const uint32_t sBh = sb + OFF_BH + boff, sBl = sb + OFF_BL + boff;

#pragma unroll
    for (int ks = 0; ks < 8; ks++) {
        const uint32_t kb = ks * 32;
        uint32_t ah[2][4], al[2][4], bh[4][4], bl[4][4];
#pragma unroll
        for (int mb = 0; mb < 2; mb++) {
            ldm4(ah[mb], sAh + kb + mb * (16 * ROWB));
            ldm4(al[mb], sAl + kb + mb * (16 * ROWB));
        }
#pragma unroll
        for (int ng = 0; ng < 4; ng++) {
            ldm4(bh[ng], sBh + kb + ng * (16 * ROWB));
            ldm4(bl[ng], sBl + kb + ng * (16 * ROWB));
        }
#pragma unroll
        for (int mb = 0; mb < 2; mb++)
#pragma unroll
            for (int ng = 0; ng < 4; ng++) {
                mma_bf16(c[mb][2 * ng],     ah[mb], bh[ng][0], bh[ng][1]);
                mma_bf16(c[mb][2 * ng],     ah[mb], bl[ng][0], bl[ng][1]);
                mma_bf16(c[mb][2 * ng],     al[mb], bh[ng][0], bh[ng][1]);
                mma_bf16(c[mb][2 * ng + 1], ah[mb], bh[ng][2], bh[ng][3]);
                mma_bf16(c[mb][2 * ng + 1], ah[mb], bl[ng][2], bl[ng][3]);
                mma_bf16(c[mb][2 * ng + 1], al[mb], bh[ng][2], bh[ng][3]);
            }
    }

    // ---- epilogue ----------------------------------------------------------
    const int q = lane >> 2, t2 = (lane & 3) * 2;
#pragma unroll
    for (int mb = 0; mb < 2; mb++) {
        const int r0 = rowbase + wm * 32 + mb * 16 + q;
        const int r1 = r0 + 8;
        if (EPI == 0) {
#pragma unroll
            for (int nt = 0; nt < 8; nt++) {
                int col = wn * 64 + nt * 8 + t2;
                *(float2*)(C + (size_t)r0 * DD + col) = make_float2(c[mb][nt][0], c[mb][nt][1]);
                *(float2*)(C + (size_t)r1 * DD + col) = make_float2(c[mb][nt][2], c[mb][nt][3]);
            }
        } else if (EPI == 2) {
#pragma unroll
            for (int nt = 0; nt < 8; nt++) {
                int col = wn * 64 + nt * 8 + t2;
                float2 bb = *(const float2*)(bias + col);
                *(float2*)(C + (size_t)r0 * DD + col) =
                    make_float2(fmaxf(c[mb][nt][0] + bb.x, 0.f), fmaxf(c[mb][nt][1] + bb.y, 0.f));
                *(float2*)(C + (size_t)r1 * DD + col) =
                    make_float2(fmaxf(c[mb][nt][2] + bb.x, 0.f), fmaxf(c[mb][nt][3] + bb.y, 0.f));
            }
        } else {
            int s0 = src[r0], d0 = dst[r0];
            int s1 = src[r1], d1 = dst[r1];
            float p0 = 0.f, p1 = 0.f;
#pragma unroll
            for (int nt = 0; nt < 8; nt++) {
                int col = wn * 64 + nt * 8 + t2;
                float2 bb = *(const float2*)(bias + col);
                float2 aa = *(const float2*)(attn + col);
                float2 x0 = *(const float2*)(fni + (size_t)s0 * DD + col);
                float2 y0 = *(const float2*)(fnj + (size_t)d0 * DD + col);
                float2 x1 = *(const float2*)(fni + (size_t)s1 * DD + col);
                float2 y1 = *(const float2*)(fnj + (size_t)d1 * DD + col);
                float v0 = c[mb][nt][0] + x0.x + y0.x + bb.x;
                float v1 = c[mb][nt][1] + x0.y + y0.y + bb.y;
                float v2 = c[mb][nt][2] + x1.x + y1.x + bb.x;
                float v3 = c[mb][nt][3] + x1.y + y1.y + bb.y;
                v0 = v0 > 0.f ? v0 : 0.01f * v0;
                v1 = v1 > 0.f ? v1 : 0.01f * v1;
                v2 = v2 > 0.f ? v2 : 0.01f * v2;
                v3 = v3 > 0.f ? v3 : 0.01f * v3;
                p0 = fmaf(v0, aa.x, p0); p0 = fmaf(v1, aa.y, p0);
                p1 = fmaf(v2, aa.x, p1); p1 = fmaf(v3, aa.y, p1);
                *(float2*)(C + (size_t)r0 * DD + col) = make_float2(v0, v1);
                *(float2*)(C + (size_t)r1 * DD + col) = make_float2(v2, v3);
            }
            p0 += __shfl_xor_sync(0xffffffffu, p0, 1);
            p0 += __shfl_xor_sync(0xffffffffu, p0, 2);
            p1 += __shfl_xor_sync(0xffffffffu, p1, 1);
            p1 += __shfl_xor_sync(0xffffffffu, p1, 2);
            if ((lane & 3) == 0 && wn == 0) { score[r0] = p0; score[r1] = p1; }
            else if ((lane & 3) == 0) {
                // second N-half: accumulate via atomic-free two-phase is overkill;
                // use atomicAdd into score (only 2 adders per row)
                atomicAdd(&score[r0], p0);
                atomicAdd(&score[r1], p1);
            }
        }
    }
}

// ---------------- CSR build -------------------------------------------------
__global__ void k_zero_deg() {
    int i = blockIdx.x * blockDim.x + threadIdx.x;
    if (i < NN) g_deg[i] = 0;
}
__global__ void k_count(const int* __restrict__ dst) {
    int e = blockIdx.x * blockDim.x + threadIdx.x;
    if (e < EE) atomicAdd(&g_deg[dst[e]], 1);
}
__global__ void k_scan() {
    __shared__ int ssum[1024];
    int t = threadIdx.x;
    int start = t * 25;
    int vals[25];
    int local = 0;
#pragma unroll
    for (int i = 0; i < 25; i++) { vals[i] = g_deg[start + i]; local += vals[i]; }
    ssum[t] = local;
    __syncthreads();
    for (int off = 1; off < 1024; off <<= 1) {
        int v = (t >= off) ? ssum[t - off] : 0;
        __syncthreads();
        ssum[t] += v;
        __syncthreads();
    }
    int prefix = (t == 0) ? 0 : ssum[t - 1];
#pragma unroll
    for (int i = 0; i < 25; i++) { g_rowptr[start + i] = prefix; prefix += vals[i]; }
    if (t == 1023) g_rowptr[NN] = prefix;
}
__global__ void k_cursor() {
    int i = blockIdx.x * blockDim.x + threadIdx.x;
    if (i < NN) g_deg[i] = g_rowptr[i];
}
__global__ void k_scatter(const int* __restrict__ dst) {
    int e = blockIdx.x * blockDim.x + threadIdx.x;
    if (e < EE) {
        int p = atomicAdd(&g_deg[dst[e]], 1);
        g_eid[p] = e;
    }
}

// ---------------- embeddings ------------------------------------------------
__global__ void k_embed_h(const int* __restrict__ th, const float* __restrict__ emb) {
    int idx = blockIdx.x * blockDim.x + threadIdx.x;
    if (idx >= NN * 32) return;
    int n = idx >> 5, q = (idx & 31) << 2;
    float4 v = *(const float4*)(emb + th[n] * DD + q);
    v.x = fmaxf(v.x, 0.f); v.y = fmaxf(v.y, 0.f);
    v.z = fmaxf(v.z, 0.f); v.w = fmaxf(v.w, 0.f);
    *(float4*)&g_h[n * DD + q] = v;
}
__global__ void k_embed_e(const int* __restrict__ te, const float* __restrict__ emb) {
    int idx = blockIdx.x * blockDim.x + threadIdx.x;
    if (idx >= EE * 32) return;
    int e = idx >> 5, q = (idx & 31) << 2;
    float4 v = *(const float4*)(emb + te[e] * DD + q);
    *(float4*)&g_e0[(size_t)e * DD + q] = v;
}

// ---------------- edge softmax + aggregation --------------------------------
__global__ void k_softmax() {
    int n = blockIdx.x * 8 + (threadIdx.x >> 5);
    int lane = threadIdx.x & 31;
    int beg = g_rowptr[n], end = g_rowptr[n + 1];
    float mx = -3.0e38f;
    for (int j = beg + lane; j < end; j += 32) mx = fmaxf(mx, g_score[g_eid[j]]);
#pragma unroll
    for (int o = 16; o > 0; o >>= 1) mx = fmaxf(mx, __shfl_xor_sync(0xffffffffu, mx, o));
    float sm = 0.f;
    for (int j = beg + lane; j < end; j += 32) sm += __expf(g_score[g_eid[j]] - mx);
#pragma unroll
    for (int o = 16; o > 0; o >>= 1) sm += __shfl_xor_sync(0xffffffffu, sm, o);
    if (lane == 0) { g_m[n] = mx; g_s[n] = sm; }
}
__global__ void k_weight(const int* __restrict__ dst) {
    int e = blockIdx.x * blockDim.x + threadIdx.x;
    if (e < EE) {
        int d = dst[e];
        g_aw[e] = __expf(g_score[e] - g_m[d]) / g_s[d];
    }
}
__global__ void k_agg(const int* __restrict__ src) {
    int n = blockIdx.x * 8 + (threadIdx.x >> 5);
    int lane = threadIdx.x & 31;
    int beg = g_rowptr[n], end = g_rowptr[n + 1];
    float4 acc = {0.f, 0.f, 0.f, 0.f};
    for (int j = beg; j < end; j++) {
        int e = g_eid[j];
        float w = g_aw[e];
        int sI = src[e];
        float4 v = *(const float4*)&g_hs[sI * DD + lane * 4];
        acc.x = fmaf(w, v.x, acc.x);
        acc.y = fmaf(w, v.y, acc.y);
        acc.z = fmaf(w, v.z, acc.z);
        acc.w = fmaf(w, v.w, acc.w);
    }
    acc.x = fmaxf(acc.x, 0.f); acc.y = fmaxf(acc.y, 0.f);
    acc.z = fmaxf(acc.z, 0.f); acc.w = fmaxf(acc.w, 0.f);
    *(float4*)&g_h[n * DD + lane * 4] = acc;
}

// ---------------- SortPooling -----------------------------------------------
__global__ void k_sort() {
    __shared__ float s[128];
    int n = blockIdx.x, t = threadIdx.x;
    s[t] = g_fni[n * DD + t];
    __syncthreads();
    for (int k = 2; k <= 128; k <<= 1)
        for (int j = k >> 1; j > 0; j >>= 1) {
            int ixj = t ^ j;
            if (ixj > t) {
                float a = s[t], b = s[ixj];
                bool up = ((t & k) == 0);
                if ((a > b) == up) { s[t] = b; s[ixj] = a; }
            }
            __syncthreads();
        }
    g_hsort[n * DD + t] = s[t];
    if (t == 127) g_rowmax[n] = s[127];
}
__global__ void k_topk() {
    __shared__ float v[256];
    __shared__ int   id[256];
    int b = blockIdx.x, t = threadIdx.x;
    if (t < NPGc) { v[t] = g_rowmax[b * NPGc + t]; id[t] = t; }
    else          { v[t] = -3.0e38f;              id[t] = 1000 + t; }
    __syncthreads();
    for (int k = 2; k <= 256; k <<= 1)
        for (int j = k >> 1; j > 0; j >>= 1) {
            int ixj = t ^ j;
            if (ixj > t) {
                bool up = ((t & k) == 0);
                float va = v[t], vb = v[ixj];
                int ia = id[t], ib = id[ixj];
                bool aAfterB = (va < vb) || (va == vb && ia > ib);
                bool sw = up ? aAfterB : !aAfterB;
                if (sw) { v[t] = vb; v[ixj] = va; id[t] = ib; id[ixj] = ia; }
            }
            __syncthreads();
        }
    if (t < KK) g_topk[b * KK + t] = id[t];
}
__global__ void k_gather() {
    int idx = blockIdx.x * blockDim.x + threadIdx.x;
    if (idx >= BB * KK * DD) return;
    int b = idx >> 12;
    int rem = idx & 4095;
    int k = rem >> 7;
    int d = rem & 127;
    int node = g_topk[b * KK + k];
    g_pooled[idx] = g_hsort[(b * NPGc + node) * DD + d];
}

// ---------------- graph-level GAT + head ------------------------------------
__device__ __forceinline__ void atomicMaxF(float* addr, float val) {
    int* ia = (int*)addr;
    int old = *ia;
    while (__int_as_float(old) < val) {
        int assumed = old;
        old = atomicCAS(ia, assumed, __float_as_int(val));
        if (old == assumed) break;
    }
}
__global__ void k_ft(const float* __restrict__ W3) {
    int b = blockIdx.x, c = threadIdx.x;
    const float* pr = g_pooled + b * (KK * DD);
    float acc = 0.f;
#pragma unroll 8
    for (int kk = 0; kk < KK * DD; kk++) acc = fmaf(pr[kk], W3[kk * DD + c], acc);
    g_ft[b * DD + c] = acc;
}
__global__ void k_alar(const float* __restrict__ al3, const float* __restrict__ ar3) {
    int b = threadIdx.x;
    float a1 = 0.f, a2 = 0.f;
    for (int k = 0; k < DD; k++) {
        float f = g_ft[b * DD + k];
        a1 = fmaf(f, al3[k], a1);
        a2 = fmaf(f, ar3[k], a2);
    }
    g_al[b] = a1;
    g_ar[b] = a2;
}
__global__ void k_fg_init() {
    int i = blockIdx.x * blockDim.x + threadIdx.x;
    if (i < BB * DD) g_gagg[i] = 0.f;
    if (i < BB) { g_m2[i] = -3.0e38f; g_s2[i] = 0.f; }
}
__global__ void k_fg_score(const int* __restrict__ fs, const int* __restrict__ fd) {
    int e = blockIdx.x * blockDim.x + threadIdx.x;
    if (e < EFE) {
        float sc = g_al[fs[e]] + g_ar[fd[e]];
        sc = sc > 0.f ? sc : 0.2f * sc;
        g_sc2[e] = sc;
        atomicMaxF(&g_m2[fd[e]], sc);
    }
}
__global__ void k_fg_exp(const int* __restrict__ fd) {
    int e = blockIdx.x * blockDim.x + threadIdx.x;
    if (e < EFE) {
        float ex = __expf(g_sc2[e] - g_m2[fd[e]]);
        g_ex2[e] = ex;
        atomicAdd(&g_s2[fd[e]], ex);
    }
}
__global__ void k_fg_agg(const int* __restrict__ fs, const int* __restrict__ fd) {
    int idx = blockIdx.x * blockDim.x + threadIdx.x;
    if (idx >= EFE * 32) return;
    int e = idx >> 5, lane = idx & 31;
    float w = g_ex2[e] / g_s2[fd[e]];
    float4 v = *(const float4*)&g_ft[fs[e] * DD + lane * 4];
    float* o = &g_gagg[fd[e] * DD + lane * 4];
    atomicAdd(o + 0, w * v.x);
    atomicAdd(o + 1, w * v.y);
    atomicAdd(o + 2, w * v.z);
    atomicAdd(o + 3, w * v.w);
}
__global__ void k_gl(const float* __restrict__ b3, const float* __restrict__ Wl,
                     const float* __restrict__ bl) {
    __shared__ float sg[128];
    int b = blockIdx.x, t = threadIdx.x;
    float v = g_gagg[b * DD + t] + b3[t];
    sg[t] = fmaxf(v, 0.f);
    __syncthreads();
    float acc = bl[t];
    for (int k = 0; k < DD; k++) acc = fmaf(sg[k], Wl[k * DD + t], acc);
    g_g2[b * DD + t] = fmaxf(acc, 0.f);
}
__global__ void k_out(const float* __restrict__ Wc, const float* __restrict__ bc,
                      float* __restrict__ out) {
    int i = threadIdx.x;
    if (i < BB * 2) {
        int b = i >> 1, c = i & 1;
        float acc = bc[c];
        for (int k = 0; k < DD; k++) acc = fmaf(g_g2[b * DD + k], Wc[k * 2 + c], acc);
        out[i] = acc;
    }
}

// ---------------- launch ----------------------------------------------------
extern "C" void kernel_launch(void* const* d_in, const int* in_sizes, int n_in,
                              void* d_out, int out_size) {
    const int*   tokens_h   = (const int*)d_in[0];
    const int*   tokens_e   = (const int*)d_in[1];
    const int*   src        = (const int*)d_in[2];
    const int*   dst        = (const int*)d_in[3];
    const int*   fg_src     = (const int*)d_in[4];
    const int*   fg_dst     = (const int*)d_in[5];
    const float* token_emb  = (const float*)d_in[6];
    const float* e_token_emb= (const float*)d_in[7];
    const float* W_ni       = (const float*)d_in[8];
    const float* W_nj       = (const float*)d_in[9];
    const float* W_fij      = (const float*)d_in[10];
    const float* W_node     = (const float*)d_in[11];
    const float* attn_e     = (const float*)d_in[12];
    const float* bias_e     = (const float*)d_in[13];
    const float* Wf         = (const float*)d_in[14];
    const float* bf         = (const float*)d_in[15];
    const float* W3         = (const float*)d_in[16];
    const float* al3        = (const float*)d_in[17];
    const float* ar3        = (const float*)d_in[18];
    const float* b3         = (const float*)d_in[19];
    const float* Wl         = (const float*)d_in[20];
    const float* bl         = (const float*)d_in[21];
    const float* Wc         = (const float*)d_in[22];
    const float* bc         = (const float*)d_in[23];

    float *p_h, *p_fni, *p_fnj, *p_hs, *p_e0, *p_e1, *p_score;
    cudaGetSymbolAddress((void**)&p_h, g_h);
    cudaGetSymbolAddress((void**)&p_fni, g_fni);
    cudaGetSymbolAddress((void**)&p_fnj, g_fnj);
    cudaGetSymbolAddress((void**)&p_hs, g_hs);
    cudaGetSymbolAddress((void**)&p_e0, g_e0);
    cudaGetSymbolAddress((void**)&p_e1, g_e1);
    cudaGetSymbolAddress((void**)&p_score, g_score);

    cudaFuncSetAttribute(tc_gemm<0>, cudaFuncAttributeMaxDynamicSharedMemorySize, SMEM_SZ);
    cudaFuncSetAttribute(tc_gemm<1>, cudaFuncAttributeMaxDynamicSharedMemorySize, SMEM_SZ);
    cudaFuncSetAttribute(tc_gemm<2>, cudaFuncAttributeMaxDynamicSharedMemorySize, SMEM_SZ);

    // CSR build
    k_zero_deg<<<NN / 256, 256>>>();
    k_count<<<EE / 256, 256>>>(dst);
    k_scan<<<1, 1024>>>();
    k_cursor<<<NN / 256, 256>>>();
    k_scatter<<<EE / 256, 256>>>(dst);

    // embeddings
    k_embed_h<<<NN * 32 / 256, 256>>>(tokens_h, token_emb);
    k_embed_e<<<EE * 32 / 256, 256>>>(tokens_e, e_token_emb);

    for (int l = 0; l < LL; l++) {
        const float* Wni   = W_ni   + l * DD * DD;
        const float* Wnj   = W_nj   + l * DD * DD;
        const float* Wnode = W_node + l * DD * DD;
        const float* Wfij  = W_fij  + l * DD * DD;
        const float* bias  = bias_e + l * DD;
        const float* attn  = attn_e + l * DD;
        float* ein  = (l & 1) ? p_e1 : p_e0;
        float* eout = (l & 1) ? p_e0 : p_e1;

        k_prepW<<<64, 256>>>(Wni);
        tc_gemm<0><<<NN / 128, 256, SMEM_SZ>>>(p_h, p_fni, nullptr, nullptr,
                                               nullptr, nullptr, nullptr, nullptr, nullptr);
        k_prepW<<<64, 256>>>(Wnj);
        tc_gemm<0><<<NN / 128, 256, SMEM_SZ>>>(p_h, p_fnj, nullptr, nullptr,
                                               nullptr, nullptr, nullptr, nullptr, nullptr);
        k_prepW<<<64, 256>>>(Wnode);
        tc_gemm<0><<<NN / 128, 256, SMEM_SZ>>>(p_h, p_hs, nullptr, nullptr,
                                               nullptr, nullptr, nullptr, nullptr, nullptr);
        k_prepW<<<64, 256>>>(Wfij);
        tc_gemm<1><<<EE / 128, 256, SMEM_SZ>>>(ein, eout, p_fni, p_fnj,
                                               src, dst, bias, attn, p_score);
        k_softmax<<<NN / 8, 256>>>();
        k_weight<<<EE / 256, 256>>>(dst);
        k_agg<<<NN / 8, 256>>>(src);
    }

    // hfinal = relu(h @ Wf + bf) -> g_fni
    k_prepW<<<64, 256>>>(Wf);
    tc_gemm<2><<<NN / 128, 256, SMEM_SZ>>>(p_h, p_fni, nullptr, nullptr,
                                           nullptr, nullptr, bf, nullptr, nullptr);

    k_sort<<<NN, 128>>>();
    k_topk<<<BB, 256>>>();
    k_gather<<<BB * KK * DD / 256, 256>>>();
    k_ft<<<BB, DD>>>(W3);
    k_alar<<<1, BB>>>(al3, ar3);
    k_fg_init<<<BB * DD / 256, 256>>>();
    k_fg_score<<<EFE / 256, 256>>>(fg_src, fg_dst);
    k_fg_exp<<<EFE / 256, 256>>>(fg_dst);
    k_fg_agg<<<EFE * 32 / 256, 256>>>(fg_src, fg_dst);
    k_gl<<<BB, DD>>>(b3, Wl, bl);
    k_out<<<1, 256>>>(Wc, bc, (float*)d_out);
}

// round 10
// speedup vs baseline: 1.7159x; 1.0221x over previous
#include <cuda_runtime.h>
#include <cuda_bf16.h>
#include <cstdint>

#define NN   25600
#define EE   409600
#define BB   128
#define EFE  1024
#define DD   128
#define LL   8
#define KK   32
#define NPGc 200

// ---------------- device scratch -------------------------------------------
__device__ float g_h[NN * DD];
__device__ float g_fni[NN * DD];
__device__ float g_fnj[NN * DD];
__device__ float g_hs[NN * DD];
__device__ float g_e0[EE * DD];
__device__ float g_e1[EE * DD];
__device__ float g_score[EE];
__device__ int   g_deg[NN];
__device__ int   g_rowptr[NN + 1];
__device__ int   g_eid[EE];
__device__ float g_m[NN];
__device__ float g_s[NN];
__device__ float g_hsort[NN * DD];
__device__ float g_rowmax[NN];
__device__ int   g_topk[BB * KK];
__device__ float g_pooled[BB * KK * DD];
__device__ float g_ft[BB * DD];
__device__ float g_al[BB];
__device__ float g_ar[BB];
__device__ float g_sc2[EFE];
__device__ float g_ex2[EFE];
__device__ float g_m2[BB];
__device__ float g_s2[BB];
__device__ float g_gagg[BB * DD];
__device__ float g_g2[BB * DD];
// all 33 weight matrices, transposed + bf16-split: WT[n][k]
// slot m: 0..7 W_ni[l], 8..15 W_nj[l], 16..23 W_node[l], 24..31 W_fij[l], 32 Wf
__device__ __align__(16) __nv_bfloat16 g_wAll_hi[33 * DD * DD];
__device__ __align__(16) __nv_bfloat16 g_wAll_lo[33 * DD * DD];

// ---------------- PTX helpers (baseline ISA only: ldmatrix + mma.sync) -----
__device__ __forceinline__ uint32_t smem_u32(const void* p) {
    uint32_t a;
    asm("{ .reg .u64 t; cvta.to.shared.u64 t, %1; cvt.u32.u64 %0, t; }"
        : "=r"(a) : "l"(p));
    return a;
}
__device__ __forceinline__ void ldm4(uint32_t* r, uint32_t addr) {
    asm volatile("ldmatrix.sync.aligned.m8n8.x4.shared.b16 {%0,%1,%2,%3}, [%4];"
                 : "=r"(r[0]), "=r"(r[1]), "=r"(r[2]), "=r"(r[3]) : "r"(addr));
}
__device__ __forceinline__ void mma_bf16(float* c, const uint32_t* a,
                                         uint32_t b0, uint32_t b1) {
    asm volatile(
        "mma.sync.aligned.m16n8k16.row.col.f32.bf16.bf16.f32 "
        "{%0,%1,%2,%3}, {%4,%5,%6,%7}, {%8,%9}, {%0,%1,%2,%3};"
        : "+f"(c[0]), "+f"(c[1]), "+f"(c[2]), "+f"(c[3])
        : "r"(a[0]), "r"(a[1]), "r"(a[2]), "r"(a[3]), "r"(b0), "r"(b1));
}
__device__ __forceinline__ uint32_t packbf(__nv_bfloat16 a, __nv_bfloat16 b) {
    __nv_bfloat162 t;
    t.x = a; t.y = b;
    return *(uint32_t*)&t;
}

// ---------------- weight prep: all 33 matrices in one launch ----------------
__global__ void k_prepAll(const float* __restrict__ Wni, const float* __restrict__ Wnj,
                          const float* __restrict__ Wnode, const float* __restrict__ Wfij,
                          const float* __restrict__ Wf) {
    int idx = blockIdx.x * blockDim.x + threadIdx.x;   // 33*16384
    if (idx >= 33 * DD * DD) return;
    int m = idx >> 14, r = idx & 16383;
    const float* W;
    if (m < 8)       W = Wni   + m * DD * DD;
    else if (m < 16) W = Wnj   + (m - 8) * DD * DD;
    else if (m < 24) W = Wnode + (m - 16) * DD * DD;
    else if (m < 32) W = Wfij  + (m - 24) * DD * DD;
    else             W = Wf;
    int n = r >> 7, k = r & 127;
    float v = W[k * DD + n];
    __nv_bfloat16 hi = __float2bfloat16(v);
    float lo = v - __bfloat162float(hi);
    g_wAll_hi[m * DD * DD + n * DD + k] = hi;
    g_wAll_lo[m * DD * DD + n * DD + k] = __float2bfloat16(lo);
}

// ---------------- mma.sync GEMM: C(Mx128) = A(Mx128) @ W --------------------
// 3-term bf16 split, TERM-MAJOR inner loop (16 independent accumulators per
// term -> no RAW chains between same-accumulator MMAs).
// CTA: 128x128 tile, 256 thr (8 warps, 4x2), warp tile 32x64.
#define PADK   136                       // bf16 elements per smem row (272 B)
#define ROWB   (PADK * 2)
#define BUFSZ  (128 * ROWB)              // 34816 B
#define OFF_AH 0
#define OFF_AL BUFSZ
#define OFF_BH (2 * BUFSZ)
#define OFF_BL (3 * BUFSZ)
#define SMEM_SZ (4 * BUFSZ)              // 139264 B

template <int EPI>
__global__ void __launch_bounds__(256)
tc_gemm(const float* __restrict__ A, float* __restrict__ C,
        const __nv_bfloat16* __restrict__ wHi, const __nv_bfloat16* __restrict__ wLo,
        const float* __restrict__ fni, const float* __restrict__ fnj,
        const int* __restrict__ src, const int* __restrict__ dst,
        const float* __restrict__ bias, const float* __restrict__ attn,
        float* __restrict__ score) {
    extern __shared__ char smem[];
    const uint32_t sb = smem_u32(smem);
    const int tid = threadIdx.x;
    const int rowbase = blockIdx.x * 128;

    // ---- stage A: fp32 -> bf16 hi/lo, padded rows --------------------------
    const float* Ab = A + (size_t)rowbase * DD;
#pragma unroll
    for (int i = 0; i < 16; i++) {
        int idx = tid + (i << 8);           // 0..4095 float4 chunks
        int r = idx >> 5, k4 = (idx & 31) << 2;
        float4 v = *(const float4*)(Ab + r * DD + k4);
        __nv_bfloat16 h0 = __float2bfloat16(v.x), h1 = __float2bfloat16(v.y);
        __nv_bfloat16 h2 = __float2bfloat16(v.z), h3 = __float2bfloat16(v.w);
        __nv_bfloat16 l0 = __float2bfloat16(v.x - __bfloat162float(h0));
        __nv_bfloat16 l1 = __float2bfloat16(v.y - __bfloat162float(h1));
        __nv_bfloat16 l2 = __float2bfloat16(v.z - __bfloat162float(h2));
        __nv_bfloat16 l3 = __float2bfloat16(v.w - __bfloat162float(h3));
        uint2 hh; hh.x = packbf(h0, h1); hh.y = packbf(h2, h3);
        uint2 ll; ll.x = packbf(l0, l1); ll.y = packbf(l2, l3);
        int off = r * ROWB + k4 * 2;
        *(uint2*)(smem + OFF_AH + off) = hh;
        *(uint2*)(smem + OFF_AL + off) = ll;
    }
    // ---- stage B: pre-split WT (n-major, k contiguous) ---------------------
#pragma unroll
    for (int i = 0; i < 8; i++) {
        int idx = tid + (i << 8);           // 0..2047 uint4 chunks (8 bf16)
        int n = idx >> 4, k8 = (idx & 15) << 3;
        int off = n * ROWB + k8 * 2;
        *(uint4*)(smem + OFF_BH + off) = *(const uint4*)(wHi + n * DD + k8);
        *(uint4*)(smem + OFF_BL + off) = *(const uint4*)(wLo + n * DD + k8);
    }
    __syncthreads();

    const int wid = tid >> 5, lane = tid & 31;
    const int wm = wid & 3, wn = wid >> 2;      // warp grid 4 (M) x 2 (N)

    float c[2][8][4] = {};                       // [mblk16][ntile8][frag]

    const uint32_t aoff = (uint32_t)(wm * 32 + (lane & 15)) * ROWB + (lane >> 4) * 16;
    const uint32_t boff = (uint32_t)(wn * 64 + (lane & 7) + ((lane >> 4) & 1) * 8) * ROWB
                        + ((lane >> 3) & 1) * 16;
    const uint32_t sAh = sb + OFF_AH + aoff, sAl = sb + OFF_AL + aoff;
    const uint32_t sBh = sb + OFF_BH + boff, sBl = sb + OFF_BL + boff;

#pragma unroll
    for (int ks = 0; ks < 8; ks++) {
        const uint32_t kb = ks * 32;
        uint32_t ah[2][4], al[2][4], bh[4][4], bl[4][4];
#pragma unroll
        for (int mb = 0; mb < 2; mb++) {
            ldm4(ah[mb], sAh + kb + mb * (16 * ROWB));
            ldm4(al[mb], sAl + kb + mb * (16 * ROWB));
        }
#pragma unroll
        for (int ng = 0; ng < 4; ng++) {
            ldm4(bh[ng], sBh + kb + ng * (16 * ROWB));
            ldm4(bl[ng], sBl + kb + ng * (16 * ROWB));
        }
        // term 1: Ahi * Bhi  (16 independent accumulators)
#pragma unroll
        for (int mb = 0; mb < 2; mb++)
#pragma unroll
            for (int ng = 0; ng < 4; ng++) {
                mma_bf16(c[mb][2 * ng],     ah[mb], bh[ng][0], bh[ng][1]);
                mma_bf16(c[mb][2 * ng + 1], ah[mb], bh[ng][2], bh[ng][3]);
            }
        // term 2: Ahi * Blo
#pragma unroll
        for (int mb = 0; mb < 2; mb++)
#pragma unroll
            for (int ng = 0; ng < 4; ng++) {
                mma_bf16(c[mb][2 * ng],     ah[mb], bl[ng][0], bl[ng][1]);
                mma_bf16(c[mb][2 * ng + 1], ah[mb], bl[ng][2], bl[ng][3]);
            }
        // term 3: Alo * Bhi
#pragma unroll
        for (int mb = 0; mb < 2; mb++)
#pragma unroll
            for (int ng = 0; ng < 4; ng++) {
                mma_bf16(c[mb][2 * ng],     al[mb], bh[ng][0], bh[ng][1]);
                mma_bf16(c[mb][2 * ng + 1], al[mb], bh[ng][2], bh[ng][3]);
            }
    }

    // ---- epilogue ----------------------------------------------------------
    const int q = lane >> 2, t2 = (lane & 3) * 2;
    float* ssc = (float*)smem;                // reused for score reduction (EPI1)
    if (EPI == 1) __syncthreads();            // smem reads done; safe to reuse
#pragma unroll
    for (int mb = 0; mb < 2; mb++) {
        const int lr0 = wm * 32 + mb * 16 + q;
        const int r0 = rowbase + lr0;
        const int r1 = r0 + 8;
        if (EPI == 0) {
#pragma unroll
            for (int nt = 0; nt < 8; nt++) {
                int col = wn * 64 + nt * 8 + t2;
                *(float2*)(C + (size_t)r0 * DD + col) = make_float2(c[mb][nt][0], c[mb][nt][1]);
                *(float2*)(C + (size_t)r1 * DD + col) = make_float2(c[mb][nt][2], c[mb][nt][3]);
            }
        } else if (EPI == 2) {
#pragma unroll
            for (int nt = 0; nt < 8; nt++) {
                int col = wn * 64 + nt * 8 + t2;
                float2 bb = *(const float2*)(bias + col);
                *(float2*)(C + (size_t)r0 * DD + col) =
                    make_float2(fmaxf(c[mb][nt][0] + bb.x, 0.f), fmaxf(c[mb][nt][1] + bb.y, 0.f));
                *(float2*)(C + (size_t)r1 * DD + col) =
                    make_float2(fmaxf(c[mb][nt][2] + bb.x, 0.f), fmaxf(c[mb][nt][3] + bb.y, 0.f));
            }
        } else {
            int s0 = src[r0], d0 = dst[r0];
            int s1 = src[r1], d1 = dst[r1];
            float p0 = 0.f, p1 = 0.f;
#pragma unroll
            for (int nt = 0; nt < 8; nt++) {
                int col = wn * 64 + nt * 8 + t2;
                float2 bb = *(const float2*)(bias + col);
                float2 aa = *(const float2*)(attn + col);
                float2 x0 = *(const float2*)(fni + (size_t)s0 * DD + col);
                float2 y0 = *(const float2*)(fnj + (size_t)d0 * DD + col);
                float2 x1 = *(const float2*)(fni + (size_t)s1 * DD + col);
                float2 y1 = *(const float2*)(fnj + (size_t)d1 * DD + col);
                float v0 = c[mb][nt][0] + x0.x + y0.x + bb.x;
                float v1 = c[mb][nt][1] + x0.y + y0.y + bb.y;
                float v2 = c[mb][nt][2] + x1.x + y1.x + bb.x;
                float v3 = c[mb][nt][3] + x1.y + y1.y + bb.y;
                v0 = v0 > 0.f ? v0 : 0.01f * v0;
                v1 = v1 > 0.f ? v1 : 0.01f * v1;
                v2 = v2 > 0.f ? v2 : 0.01f * v2;
                v3 = v3 > 0.f ? v3 : 0.01f * v3;
                p0 = fmaf(v0, aa.x, p0); p0 = fmaf(v1, aa.y, p0);
                p1 = fmaf(v2, aa.x, p1); p1 = fmaf(v3, aa.y, p1);
                *(float2*)(C + (size_t)r0 * DD + col) = make_float2(v0, v1);
                *(float2*)(C + (size_t)r1 * DD + col) = make_float2(v2, v3);
            }
            p0 += __shfl_xor_sync(0xffffffffu, p0, 1);
            p0 += __shfl_xor_sync(0xffffffffu, p0, 2);
            p1 += __shfl_xor_sync(0xffffffffu, p1, 1);
            p1 += __shfl_xor_sync(0xffffffffu, p1, 2);
            if ((lane & 3) == 0) {          // deterministic 2-slot smem reduce
                ssc[wn * 128 + lr0] = p0;
                ssc[wn * 128 + lr0 + 8] = p1;
            }
        }
    }
    if (EPI == 1) {
        __syncthreads();
        if (tid < 128) score[rowbase + tid] = ssc[tid] + ssc[128 + tid];
    }
}

// ---------------- CSR build -------------------------------------------------
__global__ void k_zero_deg() {
    int i = blockIdx.x * blockDim.x + threadIdx.x;
    if (i < NN) g_deg[i] = 0;
}
__global__ void k_count(const int* __restrict__ dst) {
    int e = blockIdx.x * blockDim.x + threadIdx.x;
    if (e < EE) atomicAdd(&g_deg[dst[e]], 1);
}
__global__ void k_scan() {
    __shared__ int ssum[1024];
    int t = threadIdx.x;
    int start = t * 25;
    int vals[25];
    int local = 0;
#pragma unroll
    for (int i = 0; i < 25; i++) { vals[i] = g_deg[start + i]; local += vals[i]; }
    ssum[t] = local;
    __syncthreads();
    for (int off = 1; off < 1024; off <<= 1) {
        int v = (t >= off) ? ssum[t - off] : 0;
        __syncthreads();
        ssum[t] += v;
        __syncthreads();
    }
    int prefix = (t == 0) ? 0 : ssum[t - 1];
#pragma unroll
    for (int i = 0; i < 25; i++) { g_rowptr[start + i] = prefix; prefix += vals[i]; }
    if (t == 1023) g_rowptr[NN] = prefix;
}
__global__ void k_cursor() {
    int i = blockIdx.x * blockDim.x + threadIdx.x;
    if (i < NN) g_deg[i] = g_rowptr[i];
}
__global__ void k_scatter(const int* __restrict__ dst) {
    int e = blockIdx.x * blockDim.x + threadIdx.x;
    if (e < EE) {
        int p = atomicAdd(&g_deg[dst[e]], 1);
        g_eid[p] = e;
    }
}

// ---------------- embeddings ------------------------------------------------
__global__ void k_embed_h(const int* __restrict__ th, const float* __restrict__ emb) {
    int idx = blockIdx.x * blockDim.x + threadIdx.x;
    if (idx >= NN * 32) return;
    int n = idx >> 5, q = (idx & 31) << 2;
    float4 v = *(const float4*)(emb + th[n] * DD + q);
    v.x = fmaxf(v.x, 0.f); v.y = fmaxf(v.y, 0.f);
    v.z = fmaxf(v.z, 0.f); v.w = fmaxf(v.w, 0.f);
    *(float4*)&g_h[n * DD + q] = v;
}
__global__ void k_embed_e(const int* __restrict__ te, const float* __restrict__ emb) {
    int idx = blockIdx.x * blockDim.x + threadIdx.x;
    if (idx >= EE * 32) return;
    int e = idx >> 5, q = (idx & 31) << 2;
    float4 v = *(const float4*)(emb + te[e] * DD + q);
    *(float4*)&g_e0[(size_t)e * DD + q] = v;
}

// ---------------- edge softmax + aggregation --------------------------------
__global__ void k_softmax() {
    int n = blockIdx.x * 8 + (threadIdx.x >> 5);
    int lane = threadIdx.x & 31;
    int beg = g_rowptr[n], end = g_rowptr[n + 1];
    float mx = -3.0e38f;
    for (int j = beg + lane; j < end; j += 32) mx = fmaxf(mx, g_score[g_eid[j]]);
#pragma unroll
    for (int o = 16; o > 0; o >>= 1) mx = fmaxf(mx, __shfl_xor_sync(0xffffffffu, mx, o));
    float sm = 0.f;
    for (int j = beg + lane; j < end; j += 32) sm += __expf(g_score[g_eid[j]] - mx);
#pragma unroll
    for (int o = 16; o > 0; o >>= 1) sm += __shfl_xor_sync(0xffffffffu, sm, o);
    if (lane == 0) { g_m[n] = mx; g_s[n] = sm; }
}
// aggregation with inline softmax weight (k_weight folded in)
__global__ void k_agg(const int* __restrict__ src) {
    int n = blockIdx.x * 8 + (threadIdx.x >> 5);
    int lane = threadIdx.x & 31;
    int beg = g_rowptr[n], end = g_rowptr[n + 1];
    float m = g_m[n];
    float inv = (end > beg) ? 1.f / g_s[n] : 0.f;
    float4 acc = {0.f, 0.f, 0.f, 0.f};
    for (int j = beg; j < end; j++) {
        int e = g_eid[j];
        float w = __expf(g_score[e] - m) * inv;
        int sI = src[e];
        float4 v = *(const float4*)&g_hs[sI * DD + lane * 4];
        acc.x = fmaf(w, v.x, acc.x);
        acc.y = fmaf(w, v.y, acc.y);
        acc.z = fmaf(w, v.z, acc.z);
        acc.w = fmaf(w, v.w, acc.w);
    }
    acc.x = fmaxf(acc.x, 0.f); acc.y = fmaxf(acc.y, 0.f);
    acc.z = fmaxf(acc.z, 0.f); acc.w = fmaxf(acc.w, 0.f);
    *(float4*)&g_h[n * DD + lane * 4] = acc;
}

// ---------------- SortPooling -----------------------------------------------
__global__ void k_sort() {
    __shared__ float s[128];
    int n = blockIdx.x, t = threadIdx.x;
    s[t] = g_fni[n * DD + t];
    __syncthreads();
    for (int k = 2; k <= 128; k <<= 1)
        for (int j = k >> 1; j > 0; j >>= 1) {
            int ixj = t ^ j;
            if (ixj > t) {
                float a = s[t], b = s[ixj];
                bool up = ((t & k) == 0);
                if ((a > b) == up) { s[t] = b; s[ixj] = a; }
            }
            __syncthreads();
        }
    g_hsort[n * DD + t] = s[t];
    if (t == 127) g_rowmax[n] = s[127];
}
__global__ void k_topk() {
    __shared__ float v[256];
    __shared__ int   id[256];
    int b = blockIdx.x, t = threadIdx.x;
    if (t < NPGc) { v[t] = g_rowmax[b * NPGc + t]; id[t] = t; }
    else          { v[t] = -3.0e38f;              id[t] = 1000 + t; }
    __syncthreads();
    for (int k = 2; k <= 256; k <<= 1)
        for (int j = k >> 1; j > 0; j >>= 1) {
            int ixj = t ^ j;
            if (ixj > t) {
                bool up = ((t & k) == 0);
                float va = v[t], vb = v[ixj];
                int ia = id[t], ib = id[ixj];
                bool aAfterB = (va < vb) || (va == vb && ia > ib);
                bool sw = up ? aAfterB : !aAfterB;
                if (sw) { v[t] = vb; v[ixj] = va; id[t] = ib; id[ixj] = ia; }
            }
            __syncthreads();
        }
    if (t < KK) g_topk[b * KK + t] = id[t];
}
__global__ void k_gather() {
    int idx = blockIdx.x * blockDim.x + threadIdx.x;
    if (idx >= BB * KK * DD) return;
    int b = idx >> 12;
    int rem = idx & 4095;
    int k = rem >> 7;
    int d = rem & 127;
    int node = g_topk[b * KK + k];
    g_pooled[idx] = g_hsort[(b * NPGc + node) * DD + d];
}

// ---------------- graph-level GAT + head ------------------------------------
__device__ __forceinline__ void atomicMaxF(float* addr, float val) {
    int* ia = (int*)addr;
    int old = *ia;
    while (__int_as_float(old) < val) {
        int assumed = old;
        old = atomicCAS(ia, assumed, __float_as_int(val));
        if (old == assumed) break;
    }
}
__global__ void k_ft(const float* __restrict__ W3) {
    int b = blockIdx.x, c = threadIdx.x;
    const float* pr = g_pooled + b * (KK * DD);
    float acc = 0.f;
#pragma unroll 8
    for (int kk = 0; kk < KK * DD; kk++) acc = fmaf(pr[kk], W3[kk * DD + c], acc);
    g_ft[b * DD + c] = acc;
}
__global__ void k_alar(const float* __restrict__ al3, const float* __restrict__ ar3) {
    int b = threadIdx.x;
    float a1 = 0.f, a2 = 0.f;
    for (int k = 0; k < DD; k++) {
        float f = g_ft[b * DD + k];
        a1 = fmaf(f, al3[k], a1);
        a2 = fmaf(f, ar3[k], a2);
    }
    g_al[b] = a1;
    g_ar[b] = a2;
}
__global__ void k_fg_init() {
    int i = blockIdx.x * blockDim.x + threadIdx.x;
    if (i < BB * DD) g_gagg[i] = 0.f;
    if (i < BB) { g_m2[i] = -3.0e38f; g_s2[i] = 0.f; }
}
__global__ void k_fg_score(const int* __restrict__ fs, const int* __restrict__ fd) {
    int e = blockIdx.x * blockDim.x + threadIdx.x;
    if (e < EFE) {
        float sc = g_al[fs[e]] + g_ar[fd[e]];
        sc = sc > 0.f ? sc : 0.2f * sc;
        g_sc2[e] = sc;
        atomicMaxF(&g_m2[fd[e]], sc);
    }
}
__global__ void k_fg_exp(const int* __restrict__ fd) {
    int e = blockIdx.x * blockDim.x + threadIdx.x;
    if (e < EFE) {
        float ex = __expf(g_sc2[e] - g_m2[fd[e]]);
        g_ex2[e] = ex;
        atomicAdd(&g_s2[fd[e]], ex);
    }
}
__global__ void k_fg_agg(const int* __restrict__ fs, const int* __restrict__ fd) {
    int idx = blockIdx.x * blockDim.x + threadIdx.x;
    if (idx >= EFE * 32) return;
    int e = idx >> 5, lane = idx & 31;
    float w = g_ex2[e] / g_s2[fd[e]];
    float4 v = *(const float4*)&g_ft[fs[e] * DD + lane * 4];
    float* o = &g_gagg[fd[e] * DD + lane * 4];
    atomicAdd(o + 0, w * v.x);
    atomicAdd(o + 1, w * v.y);
    atomicAdd(o + 2, w * v.z);
    atomicAdd(o + 3, w * v.w);
}
__global__ void k_gl(const float* __restrict__ b3, const float* __restrict__ Wl,
                     const float* __restrict__ bl) {
    __shared__ float sg[128];
    int b = blockIdx.x, t = threadIdx.x;
    float v = g_gagg[b * DD + t] + b3[t];
    sg[t] = fmaxf(v, 0.f);
    __syncthreads();
    float acc = bl[t];
    for (int k = 0; k < DD; k++) acc = fmaf(sg[k], Wl[k * DD + t], acc);
    g_g2[b * DD + t] = fmaxf(acc, 0.f);
}
__global__ void k_out(const float* __restrict__ Wc, const float* __restrict__ bc,
                      float* __restrict__ out) {
    int i = threadIdx.x;
    if (i < BB * 2) {
        int b = i >> 1, c = i & 1;
        float acc = bc[c];
        for (int k = 0; k < DD; k++) acc = fmaf(g_g2[b * DD + k], Wc[k * 2 + c], acc);
        out[i] = acc;
    }
}

// ---------------- launch ----------------------------------------------------
extern "C" void kernel_launch(void* const* d_in, const int* in_sizes, int n_in,
                              void* d_out, int out_size) {
    const int*   tokens_h   = (const int*)d_in[0];
    const int*   tokens_e   = (const int*)d_in[1];
    const int*   src        = (const int*)d_in[2];
    const int*   dst        = (const int*)d_in[3];
    const int*   fg_src     = (const int*)d_in[4];
    const int*   fg_dst     = (const int*)d_in[5];
    const float* token_emb  = (const float*)d_in[6];
    const float* e_token_emb= (const float*)d_in[7];
    const float* W_ni       = (const float*)d_in[8];
    const float* W_nj       = (const float*)d_in[9];
    const float* W_fij      = (const float*)d_in[10];
    const float* W_node     = (const float*)d_in[11];
    const float* attn_e     = (const float*)d_in[12];
    const float* bias_e     = (const float*)d_in[13];
    const float* Wf         = (const float*)d_in[14];
    const float* bf         = (const float*)d_in[15];
    const float* W3         = (const float*)d_in[16];
    const float* al3        = (const float*)d_in[17];
    const float* ar3        = (const float*)d_in[18];
    const float* b3         = (const float*)d_in[19];
    const float* Wl         = (const float*)d_in[20];
    const float* bl         = (const float*)d_in[21];
    const float* Wc         = (const float*)d_in[22];
    const float* bc         = (const float*)d_in[23];

    float *p_h, *p_fni, *p_fnj, *p_e0, *p_e1, *p_score;
    __nv_bfloat16 *p_whi, *p_wlo;
    cudaGetSymbolAddress((void**)&p_h, g_h);
    cudaGetSymbolAddress((void**)&p_fni, g_fni);
    cudaGetSymbolAddress((void**)&p_fnj, g_fnj);
    cudaGetSymbolAddress((void**)&p_e0, g_e0);
    cudaGetSymbolAddress((void**)&p_e1, g_e1);
    cudaGetSymbolAddress((void**)&p_score, g_score);
    cudaGetSymbolAddress((void**)&p_whi, g_wAll_hi);
    cudaGetSymbolAddress((void**)&p_wlo, g_wAll_lo);
    float* p_hs;
    cudaGetSymbolAddress((void**)&p_hs, g_hs);

    cudaFuncSetAttribute(tc_gemm<0>, cudaFuncAttributeMaxDynamicSharedMemorySize, SMEM_SZ);
    cudaFuncSetAttribute(tc_gemm<1>, cudaFuncAttributeMaxDynamicSharedMemorySize, SMEM_SZ);
    cudaFuncSetAttribute(tc_gemm<2>, cudaFuncAttributeMaxDynamicSharedMemorySize, SMEM_SZ);

    // weight prep (all 33 matrices, one launch)
    k_prepAll<<<(33 * DD * DD + 255) / 256, 256>>>(W_ni, W_nj, W_node, W_fij, Wf);

    // CSR build
    k_zero_deg<<<NN / 256, 256>>>();
    k_count<<<EE / 256, 256>>>(dst);
    k_scan<<<1, 1024>>>();
    k_cursor<<<NN / 256, 256>>>();
    k_scatter<<<EE / 256, 256>>>(dst);

    // embeddings
    k_embed_h<<<NN * 32 / 256, 256>>>(tokens_h, token_emb);
    k_embed_e<<<EE * 32 / 256, 256>>>(tokens_e, e_token_emb);

    const int MM = DD * DD;
    for (int l = 0; l < LL; l++) {
        const float* bias = bias_e + l * DD;
        const float* attn = attn_e + l * DD;
        float* ein  = (l & 1) ? p_e1 : p_e0;
        float* eout = (l & 1) ? p_e0 : p_e1;

        tc_gemm<0><<<NN / 128, 256, SMEM_SZ>>>(p_h, p_fni,
            p_whi + (l) * MM, p_wlo + (l) * MM,
            nullptr, nullptr, nullptr, nullptr, nullptr, nullptr, nullptr);
        tc_gemm<0><<<NN / 128, 256, SMEM_SZ>>>(p_h, p_fnj,
            p_whi + (8 + l) * MM, p_wlo + (8 + l) * MM,
            nullptr, nullptr, nullptr, nullptr, nullptr, nullptr, nullptr);
        tc_gemm<0><<<NN / 128, 256, SMEM_SZ>>>(p_h, p_hs,
            p_whi + (16 + l) * MM, p_wlo + (16 + l) * MM,
            nullptr, nullptr, nullptr, nullptr, nullptr, nullptr, nullptr);
        tc_gemm<1><<<EE / 128, 256, SMEM_SZ>>>(ein, eout,
            p_whi + (24 + l) * MM, p_wlo + (24 + l) * MM,
            p_fni, p_fnj, src, dst, bias, attn, p_score);
        k_softmax<<<NN / 8, 256>>>();
        k_agg<<<NN / 8, 256>>>(src);
    }

    // hfinal = relu(h @ Wf + bf) -> g_fni
    tc_gemm<2><<<NN / 128, 256, SMEM_SZ>>>(p_h, p_fni,
        p_whi + 32 * MM, p_wlo + 32 * MM,
        nullptr, nullptr, nullptr, nullptr, bf, nullptr, nullptr);

    k_sort<<<NN, 128>>>();
    k_topk<<<BB, 256>>>();
    k_gather<<<BB * KK * DD / 256, 256>>>();
    k_ft<<<BB, DD>>>(W3);
    k_alar<<<1, BB>>>(al3, ar3);
    k_fg_init<<<BB * DD / 256, 256>>>();
    k_fg_score<<<EFE / 256, 256>>>(fg_src, fg_dst);
    k_fg_exp<<<EFE / 256, 256>>>(fg_dst);
    k_fg_agg<<<EFE * 32 / 256, 256>>>(fg_src, fg_dst);
    k_gl<<<BB, DD>>>(b3, Wl, bl);
    k_out<<<1, 256>>>(Wc, bc, (float*)d_out);
}

// round 15
// speedup vs baseline: 1.8810x; 1.0962x over previous
#include <cuda_runtime.h>
#include <cuda_bf16.h>
#include <cstdint>

#define NN   25600
#define EE   409600
#define BB   128
#define EFE  1024
#define DD   128
#define LL   8
#define KK   32
#define NPGc 200
#define ETILES 3200
#define EGRID  400

// ---------------- device scratch -------------------------------------------
__device__ float g_h[NN * DD];
__device__ float g_fni[NN * DD];
__device__ float g_fnj[NN * DD];
__device__ float g_hs[NN * DD];
__device__ float g_e0[EE * DD];
__device__ float g_e1[EE * DD];
__device__ float g_score[EE];
__device__ int   g_deg[NN];
__device__ int   g_rowptr[NN + 1];
__device__ int   g_eid[EE];
__device__ float g_m[NN];
__device__ float g_s[NN];
__device__ float g_hsort[NN * DD];
__device__ float g_rowmax[NN];
__device__ int   g_topk[BB * KK];
__device__ float g_pooled[BB * KK * DD];
__device__ float g_ft[BB * DD];
__device__ float g_al[BB];
__device__ float g_ar[BB];
__device__ float g_sc2[EFE];
__device__ float g_ex2[EFE];
__device__ float g_m2[BB];
__device__ float g_s2[BB];
__device__ float g_gagg[BB * DD];
__device__ float g_g2[BB * DD];
// all 33 weight matrices, transposed + bf16-split: WT[n][k]
// slot m: 0..7 W_ni[l], 8..15 W_nj[l], 16..23 W_node[l], 24..31 W_fij[l], 32 Wf
__device__ __align__(16) __nv_bfloat16 g_wAll_hi[33 * DD * DD];
__device__ __align__(16) __nv_bfloat16 g_wAll_lo[33 * DD * DD];

// ---------------- PTX helpers ----------------------------------------------
__device__ __forceinline__ uint32_t smem_u32(const void* p) {
    uint32_t a;
    asm("{ .reg .u64 t; cvta.to.shared.u64 t, %1; cvt.u32.u64 %0, t; }"
        : "=r"(a) : "l"(p));
    return a;
}
__device__ __forceinline__ void ldm4(uint32_t* r, uint32_t addr) {
    asm volatile("ldmatrix.sync.aligned.m8n8.x4.shared.b16 {%0,%1,%2,%3}, [%4];"
                 : "=r"(r[0]), "=r"(r[1]), "=r"(r[2]), "=r"(r[3]) : "r"(addr));
}
__device__ __forceinline__ void mma_bf16(float* c, const uint32_t* a,
                                         uint32_t b0, uint32_t b1) {
    asm volatile(
        "mma.sync.aligned.m16n8k16.row.col.f32.bf16.bf16.f32 "
        "{%0,%1,%2,%3}, {%4,%5,%6,%7}, {%8,%9}, {%0,%1,%2,%3};"
        : "+f"(c[0]), "+f"(c[1]), "+f"(c[2]), "+f"(c[3])
        : "r"(a[0]), "r"(a[1]), "r"(a[2]), "r"(a[3]), "r"(b0), "r"(b1));
}
__device__ __forceinline__ uint32_t packbf(__nv_bfloat16 a, __nv_bfloat16 b) {
    __nv_bfloat162 t;
    t.x = a; t.y = b;
    return *(uint32_t*)&t;
}

// ---------------- weight prep: all 33 matrices in one launch ----------------
__global__ void k_prepAll(const float* __restrict__ Wni, const float* __restrict__ Wnj,
                          const float* __restrict__ Wnode, const float* __restrict__ Wfij,
                          const float* __restrict__ Wf) {
    int idx = blockIdx.x * blockDim.x + threadIdx.x;
    if (idx >= 33 * DD * DD) return;
    int m = idx >> 14, r = idx & 16383;
    const float* W;
    if (m < 8)       W = Wni   + m * DD * DD;
    else if (m < 16) W = Wnj   + (m - 8) * DD * DD;
    else if (m < 24) W = Wnode + (m - 16) * DD * DD;
    else if (m < 32) W = Wfij  + (m - 24) * DD * DD;
    else             W = Wf;
    int n = r >> 7, k = r & 127;
    float v = W[k * DD + n];
    __nv_bfloat16 hi = __float2bfloat16(v);
    float lo = v - __bfloat162float(hi);
    g_wAll_hi[m * DD * DD + n * DD + k] = hi;
    g_wAll_lo[m * DD * DD + n * DD + k] = __float2bfloat16(lo);
}

// ---------------- shared GEMM building blocks -------------------------------
#define PADK   136
#define ROWB   (PADK * 2)
#define BUFSZ  (128 * ROWB)              // 34816 B
#define OFF_AH 0
#define OFF_AL BUFSZ
#define OFF_BH (2 * BUFSZ)
#define OFF_BL (3 * BUFSZ)
#define OFF_SC (4 * BUFSZ)
#define SMEM_SZ  (4 * BUFSZ)             // 139264 (node/final)
#define ESMEM_SZ (4 * BUFSZ + 1024)      // + score scratch (edge)

// load one 128x128 fp32 tile into regs (16 float4/thread)
__device__ __forceinline__ void loadA16(float4* pre, int tile,
        const float* __restrict__ Ain, const int* __restrict__ tokA,
        const float* __restrict__ embA, int tid) {
#pragma unroll
    for (int i = 0; i < 16; i++) {
        int idx = tid + (i << 8);
        int r = idx >> 5, c4 = (idx & 31) << 2;
        int R = tile * 128 + r;
        const float* base = tokA ? (embA + (size_t)tokA[R] * DD)
                                 : (Ain + (size_t)R * DD);
        pre[i] = *(const float4*)(base + c4);
    }
}
// convert regs -> bf16 hi/lo smem buffers
__device__ __forceinline__ void cvtStoreA(const float4* pre, char* smem, int tid) {
#pragma unroll
    for (int i = 0; i < 16; i++) {
        int idx = tid + (i << 8);
        int r = idx >> 5, k4 = (idx & 31) << 2;
        float4 v = pre[i];
        __nv_bfloat16 h0 = __float2bfloat16(v.x), h1 = __float2bfloat16(v.y);
        __nv_bfloat16 h2 = __float2bfloat16(v.z), h3 = __float2bfloat16(v.w);
        __nv_bfloat16 l0 = __float2bfloat16(v.x - __bfloat162float(h0));
        __nv_bfloat16 l1 = __float2bfloat16(v.y - __bfloat162float(h1));
        __nv_bfloat16 l2 = __float2bfloat16(v.z - __bfloat162float(h2));
        __nv_bfloat16 l3 = __float2bfloat16(v.w - __bfloat162float(h3));
        uint2 hh; hh.x = packbf(h0, h1); hh.y = packbf(h2, h3);
        uint2 ll; ll.x = packbf(l0, l1); ll.y = packbf(l2, l3);
        int off = r * ROWB + k4 * 2;
        *(uint2*)(smem + OFF_AH + off) = hh;
        *(uint2*)(smem + OFF_AL + off) = ll;
    }
}
// stage a 128x128 bf16 weight pair into B buffers
__device__ __forceinline__ void stageB(const __nv_bfloat16* __restrict__ wHi,
                                       const __nv_bfloat16* __restrict__ wLo,
                                       char* smem, int tid) {
#pragma unroll
    for (int i = 0; i < 8; i++) {
        int idx = tid + (i << 8);
        int n = idx >> 4, k8 = (idx & 15) << 3;
        int off = n * ROWB + k8 * 2;
        *(uint4*)(smem + OFF_BH + off) = *(const uint4*)(wHi + n * DD + k8);
        *(uint4*)(smem + OFF_BL + off) = *(const uint4*)(wLo + n * DD + k8);
    }
}
// full 3-term MMA over staged buffers -> c[2][8][4]
__device__ __forceinline__ void mmaLoop(float c[2][8][4], uint32_t sb,
                                        int wm, int wn, int lane) {
    const uint32_t aoff = (uint32_t)(wm * 32 + (lane & 15)) * ROWB + (lane >> 4) * 16;
    const uint32_t boff = (uint32_t)(wn * 64 + (lane & 7) + ((lane >> 4) & 1) * 8) * ROWB
                        + ((lane >> 3) & 1) * 16;
    const uint32_t sAh = sb + OFF_AH + aoff, sAl = sb + OFF_AL + aoff;
    const uint32_t sBh = sb + OFF_BH + boff, sBl = sb + OFF_BL + boff;
#pragma unroll
    for (int ks = 0; ks < 8; ks++) {
        const uint32_t kb = ks * 32;
        uint32_t ah[2][4], al[2][4], bh[4][4], bl[4][4];
#pragma unroll
        for (int mb = 0; mb < 2; mb++) {
            ldm4(ah[mb], sAh + kb + mb * (16 * ROWB));
            ldm4(al[mb], sAl + kb + mb * (16 * ROWB));
        }
#pragma unroll
        for (int ng = 0; ng < 4; ng++) {
            ldm4(bh[ng], sBh + kb + ng * (16 * ROWB));
            ldm4(bl[ng], sBl + kb + ng * (16 * ROWB));
        }
#pragma unroll
        for (int mb = 0; mb < 2; mb++)
#pragma unroll
            for (int ng = 0; ng < 4; ng++) {
                mma_bf16(c[mb][2 * ng],     ah[mb], bh[ng][0], bh[ng][1]);
                mma_bf16(c[mb][2 * ng + 1], ah[mb], bh[ng][2], bh[ng][3]);
            }
#pragma unroll
        for (int mb = 0; mb < 2; mb++)
#pragma unroll
            for (int ng = 0; ng < 4; ng++) {
                mma_bf16(c[mb][2 * ng],     ah[mb], bl[ng][0], bl[ng][1]);
                mma_bf16(c[mb][2 * ng + 1], ah[mb], bl[ng][2], bl[ng][3]);
            }
#pragma unroll
        for (int mb = 0; mb < 2; mb++)
#pragma unroll
            for (int ng = 0; ng < 4; ng++) {
                mma_bf16(c[mb][2 * ng],     al[mb], bh[ng][0], bh[ng][1]);
                mma_bf16(c[mb][2 * ng + 1], al[mb], bh[ng][2], bh[ng][3]);
            }
    }
}

// ---------------- persistent edge GEMM + fused epilogue ---------------------
__global__ void __launch_bounds__(256)
tc_edge(const float* __restrict__ Ain, const int* __restrict__ tokA,
        const float* __restrict__ embA, float* __restrict__ C,
        const __nv_bfloat16* __restrict__ wHi, const __nv_bfloat16* __restrict__ wLo,
        const float* __restrict__ fni, const float* __restrict__ fnj,
        const int* __restrict__ src, const int* __restrict__ dst,
        const float* __restrict__ bias, const float* __restrict__ attn,
        float* __restrict__ score) {
    extern __shared__ char smem[];
    const uint32_t sb = smem_u32(smem);
    const int tid = threadIdx.x;
    const int wid = tid >> 5, lane = tid & 31;
    const int wm = wid & 3, wn = wid >> 2;
    float* ssc = (float*)(smem + OFF_SC);

    stageB(wHi, wLo, smem, tid);         // W constant for all tiles

    float4 pre[16];
    int t = blockIdx.x;
    loadA16(pre, t, Ain, tokA, embA, tid);

    for (; t < ETILES; t += EGRID) {
        cvtStoreA(pre, smem, tid);
        __syncthreads();
        int tn = t + EGRID;
        if (tn < ETILES) loadA16(pre, tn, Ain, tokA, embA, tid);  // overlap w/ MMA

        float c[2][8][4] = {};
        mmaLoop(c, sb, wm, wn, lane);

        // epilogue: gather + bias + leaky + score
        const int rowbase = t * 128;
        const int q = lane >> 2, t2 = (lane & 3) * 2;
#pragma unroll
        for (int mb = 0; mb < 2; mb++) {
            const int lr0 = wm * 32 + mb * 16 + q;
            const int r0 = rowbase + lr0;
            const int r1 = r0 + 8;
            int s0 = src[r0], d0 = dst[r0];
            int s1 = src[r1], d1 = dst[r1];
            float p0 = 0.f, p1 = 0.f;
#pragma unroll
            for (int nt = 0; nt < 8; nt++) {
                int col = wn * 64 + nt * 8 + t2;
                float2 bb = *(const float2*)(bias + col);
                float2 aa = *(const float2*)(attn + col);
                float2 x0 = *(const float2*)(fni + (size_t)s0 * DD + col);
                float2 y0 = *(const float2*)(fnj + (size_t)d0 * DD + col);
                float2 x1 = *(const float2*)(fni + (size_t)s1 * DD + col);
                float2 y1 = *(const float2*)(fnj + (size_t)d1 * DD + col);
                float v0 = c[mb][nt][0] + x0.x + y0.x + bb.x;
                float v1 = c[mb][nt][1] + x0.y + y0.y + bb.y;
                float v2 = c[mb][nt][2] + x1.x + y1.x + bb.x;
                float v3 = c[mb][nt][3] + x1.y + y1.y + bb.y;
                v0 = v0 > 0.f ? v0 : 0.01f * v0;
                v1 = v1 > 0.f ? v1 : 0.01f * v1;
                v2 = v2 > 0.f ? v2 : 0.01f * v2;
                v3 = v3 > 0.f ? v3 : 0.01f * v3;
                p0 = fmaf(v0, aa.x, p0); p0 = fmaf(v1, aa.y, p0);
                p1 = fmaf(v2, aa.x, p1); p1 = fmaf(v3, aa.y, p1);
                *(float2*)(C + (size_t)r0 * DD + col) = make_float2(v0, v1);
                *(float2*)(C + (size_t)r1 * DD + col) = make_float2(v2, v3);
            }
            p0 += __shfl_xor_sync(0xffffffffu, p0, 1);
            p0 += __shfl_xor_sync(0xffffffffu, p0, 2);
            p1 += __shfl_xor_sync(0xffffffffu, p1, 1);
            p1 += __shfl_xor_sync(0xffffffffu, p1, 2);
            if ((lane & 3) == 0) {
                ssc[wn * 128 + lr0] = p0;
                ssc[wn * 128 + lr0 + 8] = p1;
            }
        }
        __syncthreads();   // ssc complete AND all MMA reads of A done
        if (tid < 128) score[rowbase + tid] = ssc[tid] + ssc[128 + tid];
    }
}

// ---------------- node GEMM triple: fni/fnj/hs from one A staging -----------
__global__ void __launch_bounds__(256)
tc_node3(const float* __restrict__ A,
         const __nv_bfloat16* __restrict__ w0h, const __nv_bfloat16* __restrict__ w0l,
         const __nv_bfloat16* __restrict__ w1h, const __nv_bfloat16* __restrict__ w1l,
         const __nv_bfloat16* __restrict__ w2h, const __nv_bfloat16* __restrict__ w2l,
         float* __restrict__ C0, float* __restrict__ C1, float* __restrict__ C2) {
    extern __shared__ char smem[];
    const uint32_t sb = smem_u32(smem);
    const int tid = threadIdx.x;
    const int wid = tid >> 5, lane = tid & 31;
    const int wm = wid & 3, wn = wid >> 2;
    const int rowbase = blockIdx.x * 128;

    float4 pre[16];
    loadA16(pre, blockIdx.x, A, nullptr, nullptr, tid);
    cvtStoreA(pre, smem, tid);

#pragma unroll 1
    for (int j = 0; j < 3; j++) {
        if (j) __syncthreads();            // prior MMA reads of B done
        const __nv_bfloat16* wh = (j == 0) ? w0h : (j == 1) ? w1h : w2h;
        const __nv_bfloat16* wl = (j == 0) ? w0l : (j == 1) ? w1l : w2l;
        float* C = (j == 0) ? C0 : (j == 1) ? C1 : C2;
        stageB(wh, wl, smem, tid);
        __syncthreads();

        float c[2][8][4] = {};
        mmaLoop(c, sb, wm, wn, lane);

        const int q = lane >> 2, t2 = (lane & 3) * 2;
#pragma unroll
        for (int mb = 0; mb < 2; mb++) {
            const int r0 = rowbase + wm * 32 + mb * 16 + q;
            const int r1 = r0 + 8;
#pragma unroll
            for (int nt = 0; nt < 8; nt++) {
                int col = wn * 64 + nt * 8 + t2;
                *(float2*)(C + (size_t)r0 * DD + col) = make_float2(c[mb][nt][0], c[mb][nt][1]);
                *(float2*)(C + (size_t)r1 * DD + col) = make_float2(c[mb][nt][2], c[mb][nt][3]);
            }
        }
    }
}

// ---------------- final GEMM: relu(h @ Wf + bf) -----------------------------
__global__ void __launch_bounds__(256)
tc_final(const float* __restrict__ A, float* __restrict__ C,
         const __nv_bfloat16* __restrict__ wHi, const __nv_bfloat16* __restrict__ wLo,
         const float* __restrict__ bias) {
    extern __shared__ char smem[];
    const uint32_t sb = smem_u32(smem);
    const int tid = threadIdx.x;
    const int wid = tid >> 5, lane = tid & 31;
    const int wm = wid & 3, wn = wid >> 2;
    const int rowbase = blockIdx.x * 128;

    float4 pre[16];
    loadA16(pre, blockIdx.x, A, nullptr, nullptr, tid);
    cvtStoreA(pre, smem, tid);
    stageB(wHi, wLo, smem, tid);
    __syncthreads();

    float c[2][8][4] = {};
    mmaLoop(c, sb, wm, wn, lane);

    const int q = lane >> 2, t2 = (lane & 3) * 2;
#pragma unroll
    for (int mb = 0; mb < 2; mb++) {
        const int r0 = rowbase + wm * 32 + mb * 16 + q;
        const int r1 = r0 + 8;
#pragma unroll
        for (int nt = 0; nt < 8; nt++) {
            int col = wn * 64 + nt * 8 + t2;
            float2 bb = *(const float2*)(bias + col);
            *(float2*)(C + (size_t)r0 * DD + col) =
                make_float2(fmaxf(c[mb][nt][0] + bb.x, 0.f), fmaxf(c[mb][nt][1] + bb.y, 0.f));
            *(float2*)(C + (size_t)r1 * DD + col) =
                make_float2(fmaxf(c[mb][nt][2] + bb.x, 0.f), fmaxf(c[mb][nt][3] + bb.y, 0.f));
        }
    }
}

// ---------------- CSR build -------------------------------------------------
__global__ void k_zero_deg() {
    int i = blockIdx.x * blockDim.x + threadIdx.x;
    if (i < NN) g_deg[i] = 0;
}
__global__ void k_count(const int* __restrict__ dst) {
    int e = blockIdx.x * blockDim.x + threadIdx.x;
    if (e < EE) atomicAdd(&g_deg[dst[e]], 1);
}
__global__ void k_scan() {
    __shared__ int ssum[1024];
    int t = threadIdx.x;
    int start = t * 25;
    int vals[25];
    int local = 0;
#pragma unroll
    for (int i = 0; i < 25; i++) { vals[i] = g_deg[start + i]; local += vals[i]; }
    ssum[t] = local;
    __syncthreads();
    for (int off = 1; off < 1024; off <<= 1) {
        int v = (t >= off) ? ssum[t - off] : 0;
        __syncthreads();
        ssum[t] += v;
        __syncthreads();
    }
    int prefix = (t == 0) ? 0 : ssum[t - 1];
#pragma unroll
    for (int i = 0; i < 25; i++) { g_rowptr[start + i] = prefix; prefix += vals[i]; }
    if (t == 1023) g_rowptr[NN] = prefix;
}
__global__ void k_cursor() {
    int i = blockIdx.x * blockDim.x + threadIdx.x;
    if (i < NN) g_deg[i] = g_rowptr[i];
}
__global__ void k_scatter(const int* __restrict__ dst) {
    int e = blockIdx.x * blockDim.x + threadIdx.x;
    if (e < EE) {
        int p = atomicAdd(&g_deg[dst[e]], 1);
        g_eid[p] = e;
    }
}

// ---------------- embeddings (nodes only; edge emb fused into tc_edge) ------
__global__ void k_embed_h(const int* __restrict__ th, const float* __restrict__ emb) {
    int idx = blockIdx.x * blockDim.x + threadIdx.x;
    if (idx >= NN * 32) return;
    int n = idx >> 5, q = (idx & 31) << 2;
    float4 v = *(const float4*)(emb + th[n] * DD + q);
    v.x = fmaxf(v.x, 0.f); v.y = fmaxf(v.y, 0.f);
    v.z = fmaxf(v.z, 0.f); v.w = fmaxf(v.w, 0.f);
    *(float4*)&g_h[n * DD + q] = v;
}

// ---------------- edge softmax + aggregation --------------------------------
__global__ void k_softmax() {
    int n = blockIdx.x * 8 + (threadIdx.x >> 5);
    int lane = threadIdx.x & 31;
    int beg = g_rowptr[n], end = g_rowptr[n + 1];
    float mx = -3.0e38f;
    for (int j = beg + lane; j < end; j += 32) mx = fmaxf(mx, g_score[g_eid[j]]);
#pragma unroll
    for (int o = 16; o > 0; o >>= 1) mx = fmaxf(mx, __shfl_xor_sync(0xffffffffu, mx, o));
    float sm = 0.f;
    for (int j = beg + lane; j < end; j += 32) sm += __expf(g_score[g_eid[j]] - mx);
#pragma unroll
    for (int o = 16; o > 0; o >>= 1) sm += __shfl_xor_sync(0xffffffffu, sm, o);
    if (lane == 0) { g_m[n] = mx; g_s[n] = sm; }
}
__global__ void k_agg(const int* __restrict__ src) {
    int n = blockIdx.x * 8 + (threadIdx.x >> 5);
    int lane = threadIdx.x & 31;
    int beg = g_rowptr[n], end = g_rowptr[n + 1];
    float m = g_m[n];
    float inv = (end > beg) ? 1.f / g_s[n] : 0.f;
    float4 acc = {0.f, 0.f, 0.f, 0.f};
    for (int j = beg; j < end; j++) {
        int e = g_eid[j];
        float w = __expf(g_score[e] - m) * inv;
        int sI = src[e];
        float4 v = *(const float4*)&g_hs[sI * DD + lane * 4];
        acc.x = fmaf(w, v.x, acc.x);
        acc.y = fmaf(w, v.y, acc.y);
        acc.z = fmaf(w, v.z, acc.z);
        acc.w = fmaf(w, v.w, acc.w);
    }
    acc.x = fmaxf(acc.x, 0.f); acc.y = fmaxf(acc.y, 0.f);
    acc.z = fmaxf(acc.z, 0.f); acc.w = fmaxf(acc.w, 0.f);
    *(float4*)&g_h[n * DD + lane * 4] = acc;
}

// ---------------- SortPooling -----------------------------------------------
__global__ void k_sort() {
    __shared__ float s[128];
    int n = blockIdx.x, t = threadIdx.x;
    s[t] = g_fni[n * DD + t];
    __syncthreads();
    for (int k = 2; k <= 128; k <<= 1)
        for (int j = k >> 1; j > 0; j >>= 1) {
            int ixj = t ^ j;
            if (ixj > t) {
                float a = s[t], b = s[ixj];
                bool up = ((t & k) == 0);
                if ((a > b) == up) { s[t] = b; s[ixj] = a; }
            }
            __syncthreads();
        }
    g_hsort[n * DD + t] = s[t];
    if (t == 127) g_rowmax[n] = s[127];
}
__global__ void k_topk() {
    __shared__ float v[256];
    __shared__ int   id[256];
    int b = blockIdx.x, t = threadIdx.x;
    if (t < NPGc) { v[t] = g_rowmax[b * NPGc + t]; id[t] = t; }
    else          { v[t] = -3.0e38f;              id[t] = 1000 + t; }
    __syncthreads();
    for (int k = 2; k <= 256; k <<= 1)
        for (int j = k >> 1; j > 0; j >>= 1) {
            int ixj = t ^ j;
            if (ixj > t) {
                bool up = ((t & k) == 0);
                float va = v[t], vb = v[ixj];
                int ia = id[t], ib = id[ixj];
                bool aAfterB = (va < vb) || (va == vb && ia > ib);
                bool sw = up ? aAfterB : !aAfterB;
                if (sw) { v[t] = vb; v[ixj] = va; id[t] = ib; id[ixj] = ia; }
            }
            __syncthreads();
        }
    if (t < KK) g_topk[b * KK + t] = id[t];
}
__global__ void k_gather() {
    int idx = blockIdx.x * blockDim.x + threadIdx.x;
    if (idx >= BB * KK * DD) return;
    int b = idx >> 12;
    int rem = idx & 4095;
    int k = rem >> 7;
    int d = rem & 127;
    int node = g_topk[b * KK + k];
    g_pooled[idx] = g_hsort[(b * NPGc + node) * DD + d];
}

// ---------------- graph-level GAT + head ------------------------------------
__device__ __forceinline__ void atomicMaxF(float* addr, float val) {
    int* ia = (int*)addr;
    int old = *ia;
    while (__int_as_float(old) < val) {
        int assumed = old;
        old = atomicCAS(ia, assumed, __float_as_int(val));
        if (old == assumed) break;
    }
}
__global__ void k_ft(const float* __restrict__ W3) {
    int b = blockIdx.x, c = threadIdx.x;
    const float* pr = g_pooled + b * (KK * DD);
    float acc = 0.f;
#pragma unroll 8
    for (int kk = 0; kk < KK * DD; kk++) acc = fmaf(pr[kk], W3[kk * DD + c], acc);
    g_ft[b * DD + c] = acc;
}
__global__ void k_alar(const float* __restrict__ al3, const float* __restrict__ ar3) {
    int b = threadIdx.x;
    float a1 = 0.f, a2 = 0.f;
    for (int k = 0; k < DD; k++) {
        float f = g_ft[b * DD + k];
        a1 = fmaf(f, al3[k], a1);
        a2 = fmaf(f, ar3[k], a2);
    }
    g_al[b] = a1;
    g_ar[b] = a2;
}
__global__ void k_fg_init() {
    int i = blockIdx.x * blockDim.x + threadIdx.x;
    if (i < BB * DD) g_gagg[i] = 0.f;
    if (i < BB) { g_m2[i] = -3.0e38f; g_s2[i] = 0.f; }
}
__global__ void k_fg_score(const int* __restrict__ fs, const int* __restrict__ fd) {
    int e = blockIdx.x * blockDim.x + threadIdx.x;
    if (e < EFE) {
        float sc = g_al[fs[e]] + g_ar[fd[e]];
        sc = sc > 0.f ? sc : 0.2f * sc;
        g_sc2[e] = sc;
        atomicMaxF(&g_m2[fd[e]], sc);
    }
}
__global__ void k_fg_exp(const int* __restrict__ fd) {
    int e = blockIdx.x * blockDim.x + threadIdx.x;
    if (e < EFE) {
        float ex = __expf(g_sc2[e] - g_m2[fd[e]]);
        g_ex2[e] = ex;
        atomicAdd(&g_s2[fd[e]], ex);
    }
}
__global__ void k_fg_agg(const int* __restrict__ fs, const int* __restrict__ fd) {
    int idx = blockIdx.x * blockDim.x + threadIdx.x;
    if (idx >= EFE * 32) return;
    int e = idx >> 5, lane = idx & 31;
    float w = g_ex2[e] / g_s2[fd[e]];
    float4 v = *(const float4*)&g_ft[fs[e] * DD + lane * 4];
    float* o = &g_gagg[fd[e] * DD + lane * 4];
    atomicAdd(o + 0, w * v.x);
    atomicAdd(o + 1, w * v.y);
    atomicAdd(o + 2, w * v.z);
    atomicAdd(o + 3, w * v.w);
}
__global__ void k_gl(const float* __restrict__ b3, const float* __restrict__ Wl,
                     const float* __restrict__ bl) {
    __shared__ float sg[128];
    int b = blockIdx.x, t = threadIdx.x;
    float v = g_gagg[b * DD + t] + b3[t];
    sg[t] = fmaxf(v, 0.f);
    __syncthreads();
    float acc = bl[t];
    for (int k = 0; k < DD; k++) acc = fmaf(sg[k], Wl[k * DD + t], acc);
    g_g2[b * DD + t] = fmaxf(acc, 0.f);
}
__global__ void k_out(const float* __restrict__ Wc, const float* __restrict__ bc,
                      float* __restrict__ out) {
    int i = threadIdx.x;
    if (i < BB * 2) {
        int b = i >> 1, c = i & 1;
        float acc = bc[c];
        for (int k = 0; k < DD; k++) acc = fmaf(g_g2[b * DD + k], Wc[k * 2 + c], acc);
        out[i] = acc;
    }
}

// ---------------- launch ----------------------------------------------------
extern "C" void kernel_launch(void* const* d_in, const int* in_sizes, int n_in,
                              void* d_out, int out_size) {
    const int*   tokens_h   = (const int*)d_in[0];
    const int*   tokens_e   = (const int*)d_in[1];
    const int*   src        = (const int*)d_in[2];
    const int*   dst        = (const int*)d_in[3];
    const int*   fg_src     = (const int*)d_in[4];
    const int*   fg_dst     = (const int*)d_in[5];
    const float* token_emb  = (const float*)d_in[6];
    const float* e_token_emb= (const float*)d_in[7];
    const float* W_ni       = (const float*)d_in[8];
    const float* W_nj       = (const float*)d_in[9];
    const float* W_fij      = (const float*)d_in[10];
    const float* W_node     = (const float*)d_in[11];
    const float* attn_e     = (const float*)d_in[12];
    const float* bias_e     = (const float*)d_in[13];
    const float* Wf         = (const float*)d_in[14];
    const float* bf         = (const float*)d_in[15];
    const float* W3         = (const float*)d_in[16];
    const float* al3        = (const float*)d_in[17];
    const float* ar3        = (const float*)d_in[18];
    const float* b3         = (const float*)d_in[19];
    const float* Wl         = (const float*)d_in[20];
    const float* bl         = (const float*)d_in[21];
    const float* Wc         = (const float*)d_in[22];
    const float* bc         = (const float*)d_in[23];

    float *p_h, *p_fni, *p_fnj, *p_hs, *p_e0, *p_e1, *p_score;
    __nv_bfloat16 *p_whi, *p_wlo;
    cudaGetSymbolAddress((void**)&p_h, g_h);
    cudaGetSymbolAddress((void**)&p_fni, g_fni);
    cudaGetSymbolAddress((void**)&p_fnj, g_fnj);
    cudaGetSymbolAddress((void**)&p_hs, g_hs);
    cudaGetSymbolAddress((void**)&p_e0, g_e0);
    cudaGetSymbolAddress((void**)&p_e1, g_e1);
    cudaGetSymbolAddress((void**)&p_score, g_score);
    cudaGetSymbolAddress((void**)&p_whi, g_wAll_hi);
    cudaGetSymbolAddress((void**)&p_wlo, g_wAll_lo);

    cudaFuncSetAttribute(tc_edge,  cudaFuncAttributeMaxDynamicSharedMemorySize, ESMEM_SZ);
    cudaFuncSetAttribute(tc_node3, cudaFuncAttributeMaxDynamicSharedMemorySize, SMEM_SZ);
    cudaFuncSetAttribute(tc_final, cudaFuncAttributeMaxDynamicSharedMemorySize, SMEM_SZ);

    k_prepAll<<<(33 * DD * DD + 255) / 256, 256>>>(W_ni, W_nj, W_node, W_fij, Wf);

    // CSR build
    k_zero_deg<<<NN / 256, 256>>>();
    k_count<<<EE / 256, 256>>>(dst);
    k_scan<<<1, 1024>>>();
    k_cursor<<<NN / 256, 256>>>();
    k_scatter<<<EE / 256, 256>>>(dst);

    // node embeddings (edge embeddings are gathered inside layer-0 tc_edge)
    k_embed_h<<<NN * 32 / 256, 256>>>(tokens_h, token_emb);

    const int MM = DD * DD;
    for (int l = 0; l < LL; l++) {
        const float* bias = bias_e + l * DD;
        const float* attn = attn_e + l * DD;
        const float* ein  = (l == 0) ? nullptr : ((l & 1) ? p_e1 : p_e0);
        float* eout       = (l & 1) ? p_e0 : p_e1;
        const int* tokA   = (l == 0) ? tokens_e : nullptr;

        tc_node3<<<NN / 128, 256, SMEM_SZ>>>(p_h,
            p_whi + l * MM,        p_wlo + l * MM,
            p_whi + (8 + l) * MM,  p_wlo + (8 + l) * MM,
            p_whi + (16 + l) * MM, p_wlo + (16 + l) * MM,
            p_fni, p_fnj, p_hs);
        tc_edge<<<EGRID, 256, ESMEM_SZ>>>(ein, tokA, e_token_emb, eout,
            p_whi + (24 + l) * MM, p_wlo + (24 + l) * MM,
            p_fni, p_fnj, src, dst, bias, attn, p_score);
        k_softmax<<<NN / 8, 256>>>();
        k_agg<<<NN / 8, 256>>>(src);
    }

    tc_final<<<NN / 128, 256, SMEM_SZ>>>(p_h, p_fni,
        p_whi + 32 * MM, p_wlo + 32 * MM, bf);

    k_sort<<<NN, 128>>>();
    k_topk<<<BB, 256>>>();
    k_gather<<<BB * KK * DD / 256, 256>>>();
    k_ft<<<BB, DD>>>(W3);
    k_alar<<<1, BB>>>(al3, ar3);
    k_fg_init<<<BB * DD / 256, 256>>>();
    k_fg_score<<<EFE / 256, 256>>>(fg_src, fg_dst);
    k_fg_exp<<<EFE / 256, 256>>>(fg_dst);
    k_fg_agg<<<EFE * 32 / 256, 256>>>(fg_src, fg_dst);
    k_gl<<<BB, DD>>>(b3, Wl, bl);
    k_out<<<1, 256>>>(Wc, bc, (float*)d_out);
}